// round 1
// baseline (speedup 1.0000x reference)
#include <cuda_runtime.h>
#include <math.h>

#define B 128
#define S 400
#define H 256
#define E 128
#define V 50000
#define OOV 50
#define TWOH 512
#define VO (V + OOV)

// Output layout (flattened tuple, float32):
// final_dist [B,VO], h_t [B,H], c_t [B,H], ctx [B,2H], a_t [B,S], gen_p [B,1], next_coverage [B,S]
#define OFF_HT   (B * VO)
#define OFF_CT   (OFF_HT + B * H)
#define OFF_CTX  (OFF_CT + B * H)
#define OFF_AT   (OFF_CTX + B * TWOH)
#define OFF_GP   (OFF_AT + B * S)
#define OFF_COV  (OFF_GP + B)

// Scratch (static device arrays; no runtime allocation)
__device__ float g_status[B * TWOH];
__device__ float g_decbase[B * TWOH];   // dec_feat + att_bc
__device__ float g_gpart[B];            // gen_p pre-sigmoid partial (ws*status + wx*x + all biases)
__device__ float g_et[B * S];
__device__ float g_hidden[B * H];
__device__ float g_logits[(size_t)B * V];
__device__ float g_rowmax[B];
__device__ float g_rowinv[B];

__device__ __forceinline__ float sigf(float x) { return 1.0f / (1.0f + expf(-x)); }

// ---------------------------------------------------------------------------
// K1: embedding + input projection + LSTM cell + dec_feat precombine + gen_p partial
// grid=(B), block=(256)
// ---------------------------------------------------------------------------
__global__ void k1_lstm(
    const int* __restrict__ idx, const float* __restrict__ h0, const float* __restrict__ c0,
    const float* __restrict__ ctxv, const float* __restrict__ emb,
    const float* __restrict__ Wi, const float* __restrict__ bi,
    const float* __restrict__ W_ih, const float* __restrict__ W_hh,
    const float* __restrict__ b_ih, const float* __restrict__ b_hh,
    const float* __restrict__ att_ws, const float* __restrict__ att_bc,
    const float* __restrict__ gp_ws, const float* __restrict__ gp_bs,
    const float* __restrict__ gp_wx, const float* __restrict__ gp_bx,
    const float* __restrict__ gp_bh,
    float* __restrict__ out)
{
    const int b = blockIdx.x;
    const int t = threadIdx.x;  // 256

    __shared__ float s_in[TWOH + E];   // [context_vec, embed] (640)
    __shared__ float s_x[E];
    __shared__ float s_h0[H];
    __shared__ float s_gates[4 * H];
    __shared__ float s_st[TWOH];
    __shared__ float s_red[256];

    for (int k = t; k < TWOH; k += 256) s_in[k] = ctxv[b * TWOH + k];
    if (t < E) s_in[TWOH + t] = emb[(size_t)idx[b] * E + t];
    if (t < H) s_h0[t] = h0[b * H + t];
    __syncthreads();

    // x = Wi @ [ctx, emb] + bi   (E outputs)
    if (t < E) {
        float acc = bi[t];
        const float* w = Wi + (size_t)t * (TWOH + E);
        #pragma unroll 8
        for (int k = 0; k < TWOH + E; k++) acc += w[k] * s_in[k];
        s_x[t] = acc;
    }
    __syncthreads();

    // gates = W_ih @ x + W_hh @ h0 + biases  (4H outputs)
    for (int g = t; g < 4 * H; g += 256) {
        float acc = b_ih[g] + b_hh[g];
        const float* wi = W_ih + (size_t)g * E;
        #pragma unroll 8
        for (int k = 0; k < E; k++) acc += wi[k] * s_x[k];
        const float* wh = W_hh + (size_t)g * H;
        #pragma unroll 8
        for (int k = 0; k < H; k++) acc += wh[k] * s_h0[k];
        s_gates[g] = acc;
    }
    __syncthreads();

    // LSTM cell (torch gate order i,f,g,o)
    if (t < H) {
        float ig = sigf(s_gates[t]);
        float fg = sigf(s_gates[H + t]);
        float gg = tanhf(s_gates[2 * H + t]);
        float og = sigf(s_gates[3 * H + t]);
        float c  = fg * c0[b * H + t] + ig * gg;
        float h  = og * tanhf(c);
        out[OFF_HT + b * H + t] = h;
        out[OFF_CT + b * H + t] = c;
        s_st[t] = h;
        s_st[H + t] = c;
        g_status[b * TWOH + t] = h;
        g_status[b * TWOH + H + t] = c;
    }
    __syncthreads();

    // decbase = att_ws @ status + att_bc
    for (int j = t; j < TWOH; j += 256) {
        float acc = att_bc[j];
        const float* w = att_ws + (size_t)j * TWOH;
        #pragma unroll 8
        for (int k = 0; k < TWOH; k++) acc += w[k] * s_st[k];
        g_decbase[b * TWOH + j] = acc;
    }

    // gen_p partial: gp_ws.status + gp_wx.x + all biases
    float p = 0.0f;
    for (int k = t; k < TWOH; k += 256) p += gp_ws[k] * s_st[k];
    for (int k = t; k < E; k += 256)    p += gp_wx[k] * s_x[k];
    s_red[t] = p;
    __syncthreads();
    for (int off = 128; off > 0; off >>= 1) {
        if (t < off) s_red[t] += s_red[t + off];
        __syncthreads();
    }
    if (t == 0) g_gpart[b] = s_red[0] + gp_bs[0] + gp_bx[0] + gp_bh[0];
}

// ---------------------------------------------------------------------------
// K2: fused attention scores.
// e_t[r] = sum_j v[j]*tanh( (EO[r,:] . Wh[j,:]) + decbase[b,j] + cov[r]*wc[j] )
// Tiled 64 rows x 64 j x 512 k SGEMM with fused tanh/v-dot reduction.
// grid=(B*S/64 = 800), block=(256) as 16x16, each thread 4x4 micro-tile.
// ---------------------------------------------------------------------------
__global__ void k2_escore(
    const float* __restrict__ EO, const float* __restrict__ Wh,
    const float* __restrict__ att_wc, const float* __restrict__ att_v,
    const float* __restrict__ coverage, const int* __restrict__ mask)
{
    __shared__ __align__(16) float As[16][68];  // [k][m], 272B rows (16B aligned)
    __shared__ __align__(16) float Ws[16][68];  // [k][j]
    __shared__ float sv[64], swc[64];
    __shared__ float esm[64][17];

    const int tid = threadIdx.x;
    const int tx = tid & 15, ty = tid >> 4;
    const int rl = tid >> 2, kq = tid & 3;
    const int row0 = blockIdx.x * 64;

    float ev[4] = {0.f, 0.f, 0.f, 0.f};

    for (int jt = 0; jt < 8; jt++) {
        const int j0 = jt * 64;
        __syncthreads();  // protect sv/swc vs previous epilogue
        if (tid < 64) { sv[tid] = att_v[j0 + tid]; swc[tid] = att_wc[j0 + tid]; }

        float acc[4][4];
        #pragma unroll
        for (int a = 0; a < 4; a++)
            #pragma unroll
            for (int c = 0; c < 4; c++) acc[a][c] = 0.f;

        for (int kt = 0; kt < 32; kt++) {
            const int k0 = kt * 16;
            float4 av = *(const float4*)(EO + (size_t)(row0 + rl) * TWOH + k0 + kq * 4);
            float4 wv = *(const float4*)(Wh + (size_t)(j0 + rl) * TWOH + k0 + kq * 4);
            __syncthreads();
            As[kq * 4 + 0][rl] = av.x; As[kq * 4 + 1][rl] = av.y;
            As[kq * 4 + 2][rl] = av.z; As[kq * 4 + 3][rl] = av.w;
            Ws[kq * 4 + 0][rl] = wv.x; Ws[kq * 4 + 1][rl] = wv.y;
            Ws[kq * 4 + 2][rl] = wv.z; Ws[kq * 4 + 3][rl] = wv.w;
            __syncthreads();
            #pragma unroll
            for (int k = 0; k < 16; k++) {
                float ar[4], wr[4];
                *(float4*)ar = *(const float4*)&As[k][ty * 4];
                *(float4*)wr = *(const float4*)&Ws[k][tx * 4];
                #pragma unroll
                for (int mi = 0; mi < 4; mi++)
                    #pragma unroll
                    for (int jj = 0; jj < 4; jj++)
                        acc[mi][jj] += ar[mi] * wr[jj];
            }
        }

        // epilogue: tanh + v-dot for this j-tile
        #pragma unroll
        for (int mi = 0; mi < 4; mi++) {
            const int r = row0 + ty * 4 + mi;
            const int bb = r / S;
            const float cov = coverage[r];
            const float* db = g_decbase + (size_t)bb * TWOH + j0 + tx * 4;
            #pragma unroll
            for (int jj = 0; jj < 4; jj++) {
                float val = acc[mi][jj] + db[jj] + cov * swc[tx * 4 + jj];
                ev[mi] += sv[tx * 4 + jj] * tanhf(val);
            }
        }
    }

    __syncthreads();
    #pragma unroll
    for (int mi = 0; mi < 4; mi++) esm[ty * 4 + mi][tx] = ev[mi];
    __syncthreads();
    if (tid < 64) {
        float s = 0.f;
        #pragma unroll
        for (int t2 = 0; t2 < 16; t2++) s += esm[tid][t2];
        const int r = row0 + tid;
        g_et[r] = (mask[r] == 0) ? -1e30f : s;
    }
}

// ---------------------------------------------------------------------------
// K3: masked softmax over S, a_t, next_coverage, ctx, gen_p.
// grid=(B), block=(512)
// ---------------------------------------------------------------------------
__global__ void k3_softmax_ctx(
    const float* __restrict__ EO, const float* __restrict__ coverage,
    const float* __restrict__ gp_wh, float* __restrict__ out)
{
    const int b = blockIdx.x;
    const int t = threadIdx.x;  // 512

    __shared__ float sa[S];
    __shared__ float red[512];

    float e = (t < S) ? g_et[b * S + t] : -1e30f;
    red[t] = e;
    __syncthreads();
    for (int off = 256; off > 0; off >>= 1) {
        if (t < off) red[t] = fmaxf(red[t], red[t + off]);
        __syncthreads();
    }
    const float mx = red[0];
    __syncthreads();

    float ex = (t < S) ? expf(e - mx) : 0.f;
    red[t] = ex;
    __syncthreads();
    for (int off = 256; off > 0; off >>= 1) {
        if (t < off) red[t] += red[t + off];
        __syncthreads();
    }
    const float inv = 1.f / red[0];
    __syncthreads();

    if (t < S) {
        float a = ex * inv;
        sa[t] = a;
        out[OFF_AT + b * S + t] = a;
        out[OFF_COV + b * S + t] = coverage[b * S + t] + a;
    }
    __syncthreads();

    // ctx[d] = sum_s a[s] * EO[b,s,d]   (d = t, 512 threads)
    const float* eob = EO + (size_t)b * S * TWOH;
    float c = 0.f;
    #pragma unroll 4
    for (int s = 0; s < S; s++) c += sa[s] * eob[(size_t)s * TWOH + t];
    out[OFF_CTX + b * TWOH + t] = c;

    // gen_p = sigmoid(gp_wh.ctx + partial)
    red[t] = gp_wh[t] * c;
    __syncthreads();
    for (int off = 256; off > 0; off >>= 1) {
        if (t < off) red[t] += red[t + off];
        __syncthreads();
    }
    if (t == 0) out[OFF_GP + b] = sigf(red[0] + g_gpart[b]);
}

// ---------------------------------------------------------------------------
// K3b: hidden = relu(out_w1 @ [h_t, ctx] + out_b1).  grid=(B), block=(256)
// ---------------------------------------------------------------------------
__global__ void k3b_hidden(
    const float* __restrict__ out_w1, const float* __restrict__ out_b1,
    const float* __restrict__ out)
{
    const int b = blockIdx.x, t = threadIdx.x;
    __shared__ float sf[H + TWOH];  // 768
    if (t < H) sf[t] = out[OFF_HT + b * H + t];
    for (int k = t; k < TWOH; k += 256) sf[H + k] = out[OFF_CTX + b * TWOH + k];
    __syncthreads();
    float acc = out_b1[t];
    const float* w = out_w1 + (size_t)t * (H + TWOH);
    #pragma unroll 8
    for (int k = 0; k < H + TWOH; k++) acc += w[k] * sf[k];
    g_hidden[b * H + t] = fmaxf(acc, 0.f);
}

// ---------------------------------------------------------------------------
// K4: logits = hidden @ out_w2.T + b2.  Tiled 64x64xK256.
// grid=(ceil(V/64)=782, 2), block=(256)
// ---------------------------------------------------------------------------
__global__ void k4_logits(const float* __restrict__ W2, const float* __restrict__ b2)
{
    __shared__ __align__(16) float As[16][68];
    __shared__ __align__(16) float Ws[16][68];

    const int tid = threadIdx.x;
    const int tx = tid & 15, ty = tid >> 4;
    const int rl = tid >> 2, kq = tid & 3;
    const int r0 = blockIdx.y * 64;
    const int j0 = blockIdx.x * 64;

    float acc[4][4];
    #pragma unroll
    for (int a = 0; a < 4; a++)
        #pragma unroll
        for (int c = 0; c < 4; c++) acc[a][c] = 0.f;

    for (int kt = 0; kt < 16; kt++) {
        const int k0 = kt * 16;
        float4 av = *(const float4*)(g_hidden + (size_t)(r0 + rl) * H + k0 + kq * 4);
        const int jg = j0 + rl;
        float4 wv = make_float4(0.f, 0.f, 0.f, 0.f);
        if (jg < V) wv = *(const float4*)(W2 + (size_t)jg * H + k0 + kq * 4);
        __syncthreads();
        As[kq * 4 + 0][rl] = av.x; As[kq * 4 + 1][rl] = av.y;
        As[kq * 4 + 2][rl] = av.z; As[kq * 4 + 3][rl] = av.w;
        Ws[kq * 4 + 0][rl] = wv.x; Ws[kq * 4 + 1][rl] = wv.y;
        Ws[kq * 4 + 2][rl] = wv.z; Ws[kq * 4 + 3][rl] = wv.w;
        __syncthreads();
        #pragma unroll
        for (int k = 0; k < 16; k++) {
            float ar[4], wr[4];
            *(float4*)ar = *(const float4*)&As[k][ty * 4];
            *(float4*)wr = *(const float4*)&Ws[k][tx * 4];
            #pragma unroll
            for (int mi = 0; mi < 4; mi++)
                #pragma unroll
                for (int jj = 0; jj < 4; jj++)
                    acc[mi][jj] += ar[mi] * wr[jj];
        }
    }

    #pragma unroll
    for (int mi = 0; mi < 4; mi++) {
        const int r = r0 + ty * 4 + mi;
        #pragma unroll
        for (int jj = 0; jj < 4; jj++) {
            const int j = j0 + tx * 4 + jj;
            if (j < V) g_logits[(size_t)r * V + j] = acc[mi][jj] + b2[j];
        }
    }
}

// ---------------------------------------------------------------------------
// K5a: per-row max & inv-sumexp of logits.  grid=(B), block=(256)
// ---------------------------------------------------------------------------
__global__ void k5a_rowstats()
{
    const int b = blockIdx.x, t = threadIdx.x;
    __shared__ float red[256];
    const float* lr = g_logits + (size_t)b * V;

    float mx = -1e30f;
    for (int j = t; j < V; j += 256) mx = fmaxf(mx, lr[j]);
    red[t] = mx;
    __syncthreads();
    for (int off = 128; off > 0; off >>= 1) {
        if (t < off) red[t] = fmaxf(red[t], red[t + off]);
        __syncthreads();
    }
    mx = red[0];
    __syncthreads();

    float s = 0.f;
    for (int j = t; j < V; j += 256) s += expf(lr[j] - mx);
    red[t] = s;
    __syncthreads();
    for (int off = 128; off > 0; off >>= 1) {
        if (t < off) red[t] += red[t + off];
        __syncthreads();
    }
    if (t == 0) { g_rowmax[b] = mx; g_rowinv[b] = 1.f / red[0]; }
}

// ---------------------------------------------------------------------------
// K5b: final_dist base = softmax(logits)*gen_p, zeros in OOV tail.
// grid=(B*VO/256 = 25025), block=(256)
// ---------------------------------------------------------------------------
__global__ void k5b_final(float* __restrict__ out)
{
    const int i = blockIdx.x * 256 + threadIdx.x;
    if (i >= B * VO) return;
    const int b = i / VO;
    const int c = i - b * VO;
    float v = 0.f;
    if (c < V) {
        const float gp = out[OFF_GP + b];
        v = expf(g_logits[(size_t)b * V + c] - g_rowmax[b]) * g_rowinv[b] * gp;
    }
    out[i] = v;
}

// ---------------------------------------------------------------------------
// K5c: scatter-add a_t*(1-gen_p) at encoder_with_oov.  grid=(B*S/256), block=(256)
// ---------------------------------------------------------------------------
__global__ void k5c_scatter(const int* __restrict__ ewo, float* __restrict__ out)
{
    const int i = blockIdx.x * 256 + threadIdx.x;
    if (i >= B * S) return;
    const int b = i / S;
    const float gp = out[OFF_GP + b];
    const float a = out[OFF_AT + i];
    atomicAdd(out + (size_t)b * VO + ewo[i], a * (1.f - gp));
}

// ---------------------------------------------------------------------------
extern "C" void kernel_launch(void* const* d_in, const int* in_sizes, int n_in,
                              void* d_out, int out_size)
{
    const int*   idx      = (const int*)  d_in[0];
    const float* h0       = (const float*)d_in[1];
    const float* c0       = (const float*)d_in[2];
    const float* EO       = (const float*)d_in[3];
    const int*   emask    = (const int*)  d_in[4];
    const float* ctxv     = (const float*)d_in[5];
    // d_in[6] = oovs_zero (all zeros; tail is written as 0 directly)
    const int*   ewo      = (const int*)  d_in[7];
    const float* coverage = (const float*)d_in[8];
    const float* emb      = (const float*)d_in[9];
    const float* Wi       = (const float*)d_in[10];
    const float* bi       = (const float*)d_in[11];
    const float* W_ih     = (const float*)d_in[12];
    const float* W_hh     = (const float*)d_in[13];
    const float* b_ih     = (const float*)d_in[14];
    const float* b_hh     = (const float*)d_in[15];
    const float* att_wh   = (const float*)d_in[16];
    const float* att_ws   = (const float*)d_in[17];
    const float* att_wc   = (const float*)d_in[18];
    const float* att_bc   = (const float*)d_in[19];
    const float* att_v    = (const float*)d_in[20];
    const float* gp_wh    = (const float*)d_in[21];
    const float* gp_bh    = (const float*)d_in[22];
    const float* gp_ws    = (const float*)d_in[23];
    const float* gp_bs    = (const float*)d_in[24];
    const float* gp_wx    = (const float*)d_in[25];
    const float* gp_bx    = (const float*)d_in[26];
    const float* out_w1   = (const float*)d_in[27];
    const float* out_b1   = (const float*)d_in[28];
    const float* out_w2   = (const float*)d_in[29];
    const float* out_b2   = (const float*)d_in[30];
    float* out = (float*)d_out;

    k1_lstm<<<B, 256>>>(idx, h0, c0, ctxv, emb, Wi, bi, W_ih, W_hh, b_ih, b_hh,
                        att_ws, att_bc, gp_ws, gp_bs, gp_wx, gp_bx, gp_bh, out);
    k2_escore<<<(B * S) / 64, 256>>>(EO, att_wh, att_wc, att_v, coverage, emask);
    k3_softmax_ctx<<<B, 512>>>(EO, coverage, gp_wh, out);
    k3b_hidden<<<B, 256>>>(out_w1, out_b1, out);
    {
        dim3 grid((V + 63) / 64, 2);
        k4_logits<<<grid, 256>>>(out_w2, out_b2);
    }
    k5a_rowstats<<<B, 256>>>();
    k5b_final<<<(B * VO + 255) / 256, 256>>>(out);
    k5c_scatter<<<(B * S + 255) / 256, 256>>>(ewo, out);
}

// round 2
// speedup vs baseline: 1.0021x; 1.0021x over previous
#include <cuda_runtime.h>
#include <math.h>

#define B 128
#define S 400
#define H 256
#define E 128
#define V 50000
#define OOV 50
#define TWOH 512
#define VO (V + OOV)

// Output layout (flattened tuple, float32):
// final_dist [B,VO], h_t [B,H], c_t [B,H], ctx [B,2H], a_t [B,S], gen_p [B,1], next_coverage [B,S]
#define OFF_HT   (B * VO)
#define OFF_CT   (OFF_HT + B * H)
#define OFF_CTX  (OFF_CT + B * H)
#define OFF_AT   (OFF_CTX + B * TWOH)
#define OFF_GP   (OFF_AT + B * S)
#define OFF_COV  (OFF_GP + B)

// Scratch (static device arrays; no runtime allocation)
__device__ float g_status[B * TWOH];
__device__ float g_decbase[B * TWOH];   // dec_feat + att_bc
__device__ float g_gpart[B];            // gen_p pre-sigmoid partial (ws*status + wx*x + all biases)
__device__ float g_et[B * S];
__device__ float g_hidden[B * H];
__device__ float g_logits[(size_t)B * V];
__device__ float g_rowmax[B];
__device__ float g_rowinv[B];

__device__ __forceinline__ float sigf(float x) { return 1.0f / (1.0f + expf(-x)); }

// ---------------------------------------------------------------------------
// K1: embedding + input projection + LSTM cell + dec_feat precombine + gen_p partial
// grid=(B), block=(256)
// ---------------------------------------------------------------------------
__global__ void k1_lstm(
    const int* __restrict__ idx, const float* __restrict__ h0, const float* __restrict__ c0,
    const float* __restrict__ ctxv, const float* __restrict__ emb,
    const float* __restrict__ Wi, const float* __restrict__ bi,
    const float* __restrict__ W_ih, const float* __restrict__ W_hh,
    const float* __restrict__ b_ih, const float* __restrict__ b_hh,
    const float* __restrict__ att_ws, const float* __restrict__ att_bc,
    const float* __restrict__ gp_ws, const float* __restrict__ gp_bs,
    const float* __restrict__ gp_wx, const float* __restrict__ gp_bx,
    const float* __restrict__ gp_bh,
    float* __restrict__ out)
{
    const int b = blockIdx.x;
    const int t = threadIdx.x;  // 256

    __shared__ float s_in[TWOH + E];   // [context_vec, embed] (640)
    __shared__ float s_x[E];
    __shared__ float s_h0[H];
    __shared__ float s_gates[4 * H];
    __shared__ float s_st[TWOH];
    __shared__ float s_red[256];

    for (int k = t; k < TWOH; k += 256) s_in[k] = ctxv[b * TWOH + k];
    if (t < E) s_in[TWOH + t] = emb[(size_t)idx[b] * E + t];
    if (t < H) s_h0[t] = h0[b * H + t];
    __syncthreads();

    // x = Wi @ [ctx, emb] + bi   (E outputs)
    if (t < E) {
        float acc = bi[t];
        const float* w = Wi + (size_t)t * (TWOH + E);
        #pragma unroll 8
        for (int k = 0; k < TWOH + E; k++) acc += w[k] * s_in[k];
        s_x[t] = acc;
    }
    __syncthreads();

    // gates = W_ih @ x + W_hh @ h0 + biases  (4H outputs)
    for (int g = t; g < 4 * H; g += 256) {
        float acc = b_ih[g] + b_hh[g];
        const float* wi = W_ih + (size_t)g * E;
        #pragma unroll 8
        for (int k = 0; k < E; k++) acc += wi[k] * s_x[k];
        const float* wh = W_hh + (size_t)g * H;
        #pragma unroll 8
        for (int k = 0; k < H; k++) acc += wh[k] * s_h0[k];
        s_gates[g] = acc;
    }
    __syncthreads();

    // LSTM cell (torch gate order i,f,g,o)
    if (t < H) {
        float ig = sigf(s_gates[t]);
        float fg = sigf(s_gates[H + t]);
        float gg = tanhf(s_gates[2 * H + t]);
        float og = sigf(s_gates[3 * H + t]);
        float c  = fg * c0[b * H + t] + ig * gg;
        float h  = og * tanhf(c);
        out[OFF_HT + b * H + t] = h;
        out[OFF_CT + b * H + t] = c;
        s_st[t] = h;
        s_st[H + t] = c;
        g_status[b * TWOH + t] = h;
        g_status[b * TWOH + H + t] = c;
    }
    __syncthreads();

    // decbase = att_ws @ status + att_bc
    for (int j = t; j < TWOH; j += 256) {
        float acc = att_bc[j];
        const float* w = att_ws + (size_t)j * TWOH;
        #pragma unroll 8
        for (int k = 0; k < TWOH; k++) acc += w[k] * s_st[k];
        g_decbase[b * TWOH + j] = acc;
    }

    // gen_p partial: gp_ws.status + gp_wx.x + all biases
    float p = 0.0f;
    for (int k = t; k < TWOH; k += 256) p += gp_ws[k] * s_st[k];
    for (int k = t; k < E; k += 256)    p += gp_wx[k] * s_x[k];
    s_red[t] = p;
    __syncthreads();
    for (int off = 128; off > 0; off >>= 1) {
        if (t < off) s_red[t] += s_red[t + off];
        __syncthreads();
    }
    if (t == 0) g_gpart[b] = s_red[0] + gp_bs[0] + gp_bx[0] + gp_bh[0];
}

// ---------------------------------------------------------------------------
// K2: fused attention scores.
// e_t[r] = sum_j v[j]*tanh( (EO[r,:] . Wh[j,:]) + decbase[b,j] + cov[r]*wc[j] )
// Tiled 64 rows x 64 j x 512 k SGEMM with fused tanh/v-dot reduction.
// grid=(B*S/64 = 800), block=(256) as 16x16, each thread 4x4 micro-tile.
// ---------------------------------------------------------------------------
__global__ void k2_escore(
    const float* __restrict__ EO, const float* __restrict__ Wh,
    const float* __restrict__ att_wc, const float* __restrict__ att_v,
    const float* __restrict__ coverage, const int* __restrict__ mask)
{
    __shared__ __align__(16) float As[16][68];  // [k][m], 272B rows (16B aligned)
    __shared__ __align__(16) float Ws[16][68];  // [k][j]
    __shared__ float sv[64], swc[64];
    __shared__ float esm[64][17];

    const int tid = threadIdx.x;
    const int tx = tid & 15, ty = tid >> 4;
    const int rl = tid >> 2, kq = tid & 3;
    const int row0 = blockIdx.x * 64;

    float ev[4] = {0.f, 0.f, 0.f, 0.f};

    for (int jt = 0; jt < 8; jt++) {
        const int j0 = jt * 64;
        __syncthreads();  // protect sv/swc vs previous epilogue
        if (tid < 64) { sv[tid] = att_v[j0 + tid]; swc[tid] = att_wc[j0 + tid]; }

        float acc[4][4];
        #pragma unroll
        for (int a = 0; a < 4; a++)
            #pragma unroll
            for (int c = 0; c < 4; c++) acc[a][c] = 0.f;

        for (int kt = 0; kt < 32; kt++) {
            const int k0 = kt * 16;
            float4 av = *(const float4*)(EO + (size_t)(row0 + rl) * TWOH + k0 + kq * 4);
            float4 wv = *(const float4*)(Wh + (size_t)(j0 + rl) * TWOH + k0 + kq * 4);
            __syncthreads();
            As[kq * 4 + 0][rl] = av.x; As[kq * 4 + 1][rl] = av.y;
            As[kq * 4 + 2][rl] = av.z; As[kq * 4 + 3][rl] = av.w;
            Ws[kq * 4 + 0][rl] = wv.x; Ws[kq * 4 + 1][rl] = wv.y;
            Ws[kq * 4 + 2][rl] = wv.z; Ws[kq * 4 + 3][rl] = wv.w;
            __syncthreads();
            #pragma unroll
            for (int k = 0; k < 16; k++) {
                float ar[4], wr[4];
                *(float4*)ar = *(const float4*)&As[k][ty * 4];
                *(float4*)wr = *(const float4*)&Ws[k][tx * 4];
                #pragma unroll
                for (int mi = 0; mi < 4; mi++)
                    #pragma unroll
                    for (int jj = 0; jj < 4; jj++)
                        acc[mi][jj] += ar[mi] * wr[jj];
            }
        }

        // epilogue: tanh + v-dot for this j-tile
        #pragma unroll
        for (int mi = 0; mi < 4; mi++) {
            const int r = row0 + ty * 4 + mi;
            const int bb = r / S;
            const float cov = coverage[r];
            const float* db = g_decbase + (size_t)bb * TWOH + j0 + tx * 4;
            #pragma unroll
            for (int jj = 0; jj < 4; jj++) {
                float val = acc[mi][jj] + db[jj] + cov * swc[tx * 4 + jj];
                ev[mi] += sv[tx * 4 + jj] * tanhf(val);
            }
        }
    }

    __syncthreads();
    #pragma unroll
    for (int mi = 0; mi < 4; mi++) esm[ty * 4 + mi][tx] = ev[mi];
    __syncthreads();
    if (tid < 64) {
        float s = 0.f;
        #pragma unroll
        for (int t2 = 0; t2 < 16; t2++) s += esm[tid][t2];
        const int r = row0 + tid;
        g_et[r] = (mask[r] == 0) ? -1e30f : s;
    }
}

// ---------------------------------------------------------------------------
// K3: masked softmax over S, a_t, next_coverage, ctx, gen_p.
// grid=(B), block=(512)
// ---------------------------------------------------------------------------
__global__ void k3_softmax_ctx(
    const float* __restrict__ EO, const float* __restrict__ coverage,
    const float* __restrict__ gp_wh, float* __restrict__ out)
{
    const int b = blockIdx.x;
    const int t = threadIdx.x;  // 512

    __shared__ float sa[S];
    __shared__ float red[512];

    float e = (t < S) ? g_et[b * S + t] : -1e30f;
    red[t] = e;
    __syncthreads();
    for (int off = 256; off > 0; off >>= 1) {
        if (t < off) red[t] = fmaxf(red[t], red[t + off]);
        __syncthreads();
    }
    const float mx = red[0];
    __syncthreads();

    float ex = (t < S) ? expf(e - mx) : 0.f;
    red[t] = ex;
    __syncthreads();
    for (int off = 256; off > 0; off >>= 1) {
        if (t < off) red[t] += red[t + off];
        __syncthreads();
    }
    const float inv = 1.f / red[0];
    __syncthreads();

    if (t < S) {
        float a = ex * inv;
        sa[t] = a;
        out[OFF_AT + b * S + t] = a;
        out[OFF_COV + b * S + t] = coverage[b * S + t] + a;
    }
    __syncthreads();

    // ctx[d] = sum_s a[s] * EO[b,s,d]   (d = t, 512 threads)
    const float* eob = EO + (size_t)b * S * TWOH;
    float c = 0.f;
    #pragma unroll 4
    for (int s = 0; s < S; s++) c += sa[s] * eob[(size_t)s * TWOH + t];
    out[OFF_CTX + b * TWOH + t] = c;

    // gen_p = sigmoid(gp_wh.ctx + partial)
    red[t] = gp_wh[t] * c;
    __syncthreads();
    for (int off = 256; off > 0; off >>= 1) {
        if (t < off) red[t] += red[t + off];
        __syncthreads();
    }
    if (t == 0) out[OFF_GP + b] = sigf(red[0] + g_gpart[b]);
}

// ---------------------------------------------------------------------------
// K3b: hidden = relu(out_w1 @ [h_t, ctx] + out_b1).  grid=(B), block=(256)
// ---------------------------------------------------------------------------
__global__ void k3b_hidden(
    const float* __restrict__ out_w1, const float* __restrict__ out_b1,
    const float* __restrict__ out)
{
    const int b = blockIdx.x, t = threadIdx.x;
    __shared__ float sf[H + TWOH];  // 768
    if (t < H) sf[t] = out[OFF_HT + b * H + t];
    for (int k = t; k < TWOH; k += 256) sf[H + k] = out[OFF_CTX + b * TWOH + k];
    __syncthreads();
    float acc = out_b1[t];
    const float* w = out_w1 + (size_t)t * (H + TWOH);
    #pragma unroll 8
    for (int k = 0; k < H + TWOH; k++) acc += w[k] * sf[k];
    g_hidden[b * H + t] = fmaxf(acc, 0.f);
}

// ---------------------------------------------------------------------------
// K4: logits = hidden @ out_w2.T + b2.  Tiled 64x64xK256.
// grid=(ceil(V/64)=782, 2), block=(256)
// ---------------------------------------------------------------------------
__global__ void k4_logits(const float* __restrict__ W2, const float* __restrict__ b2)
{
    __shared__ __align__(16) float As[16][68];
    __shared__ __align__(16) float Ws[16][68];

    const int tid = threadIdx.x;
    const int tx = tid & 15, ty = tid >> 4;
    const int rl = tid >> 2, kq = tid & 3;
    const int r0 = blockIdx.y * 64;
    const int j0 = blockIdx.x * 64;

    float acc[4][4];
    #pragma unroll
    for (int a = 0; a < 4; a++)
        #pragma unroll
        for (int c = 0; c < 4; c++) acc[a][c] = 0.f;

    for (int kt = 0; kt < 16; kt++) {
        const int k0 = kt * 16;
        float4 av = *(const float4*)(g_hidden + (size_t)(r0 + rl) * H + k0 + kq * 4);
        const int jg = j0 + rl;
        float4 wv = make_float4(0.f, 0.f, 0.f, 0.f);
        if (jg < V) wv = *(const float4*)(W2 + (size_t)jg * H + k0 + kq * 4);
        __syncthreads();
        As[kq * 4 + 0][rl] = av.x; As[kq * 4 + 1][rl] = av.y;
        As[kq * 4 + 2][rl] = av.z; As[kq * 4 + 3][rl] = av.w;
        Ws[kq * 4 + 0][rl] = wv.x; Ws[kq * 4 + 1][rl] = wv.y;
        Ws[kq * 4 + 2][rl] = wv.z; Ws[kq * 4 + 3][rl] = wv.w;
        __syncthreads();
        #pragma unroll
        for (int k = 0; k < 16; k++) {
            float ar[4], wr[4];
            *(float4*)ar = *(const float4*)&As[k][ty * 4];
            *(float4*)wr = *(const float4*)&Ws[k][tx * 4];
            #pragma unroll
            for (int mi = 0; mi < 4; mi++)
                #pragma unroll
                for (int jj = 0; jj < 4; jj++)
                    acc[mi][jj] += ar[mi] * wr[jj];
        }
    }

    #pragma unroll
    for (int mi = 0; mi < 4; mi++) {
        const int r = r0 + ty * 4 + mi;
        #pragma unroll
        for (int jj = 0; jj < 4; jj++) {
            const int j = j0 + tx * 4 + jj;
            if (j < V) g_logits[(size_t)r * V + j] = acc[mi][jj] + b2[j];
        }
    }
}

// ---------------------------------------------------------------------------
// K5a: per-row max & inv-sumexp of logits.  grid=(B), block=(256)
// ---------------------------------------------------------------------------
__global__ void k5a_rowstats()
{
    const int b = blockIdx.x, t = threadIdx.x;
    __shared__ float red[256];
    const float* lr = g_logits + (size_t)b * V;

    float mx = -1e30f;
    for (int j = t; j < V; j += 256) mx = fmaxf(mx, lr[j]);
    red[t] = mx;
    __syncthreads();
    for (int off = 128; off > 0; off >>= 1) {
        if (t < off) red[t] = fmaxf(red[t], red[t + off]);
        __syncthreads();
    }
    mx = red[0];
    __syncthreads();

    float s = 0.f;
    for (int j = t; j < V; j += 256) s += expf(lr[j] - mx);
    red[t] = s;
    __syncthreads();
    for (int off = 128; off > 0; off >>= 1) {
        if (t < off) red[t] += red[t + off];
        __syncthreads();
    }
    if (t == 0) { g_rowmax[b] = mx; g_rowinv[b] = 1.f / red[0]; }
}

// ---------------------------------------------------------------------------
// K5b: final_dist base = softmax(logits)*gen_p, zeros in OOV tail.
// grid=(B*VO/256 = 25025), block=(256)
// ---------------------------------------------------------------------------
__global__ void k5b_final(float* __restrict__ out)
{
    const int i = blockIdx.x * 256 + threadIdx.x;
    if (i >= B * VO) return;
    const int b = i / VO;
    const int c = i - b * VO;
    float v = 0.f;
    if (c < V) {
        const float gp = out[OFF_GP + b];
        v = expf(g_logits[(size_t)b * V + c] - g_rowmax[b]) * g_rowinv[b] * gp;
    }
    out[i] = v;
}

// ---------------------------------------------------------------------------
// K5c: scatter-add a_t*(1-gen_p) at encoder_with_oov.  grid=(B*S/256), block=(256)
// ---------------------------------------------------------------------------
__global__ void k5c_scatter(const int* __restrict__ ewo, float* __restrict__ out)
{
    const int i = blockIdx.x * 256 + threadIdx.x;
    if (i >= B * S) return;
    const int b = i / S;
    const float gp = out[OFF_GP + b];
    const float a = out[OFF_AT + i];
    atomicAdd(out + (size_t)b * VO + ewo[i], a * (1.f - gp));
}

// ---------------------------------------------------------------------------
extern "C" void kernel_launch(void* const* d_in, const int* in_sizes, int n_in,
                              void* d_out, int out_size)
{
    const int*   idx      = (const int*)  d_in[0];
    const float* h0       = (const float*)d_in[1];
    const float* c0       = (const float*)d_in[2];
    const float* EO       = (const float*)d_in[3];
    const int*   emask    = (const int*)  d_in[4];
    const float* ctxv     = (const float*)d_in[5];
    // d_in[6] = oovs_zero (all zeros; tail is written as 0 directly)
    const int*   ewo      = (const int*)  d_in[7];
    const float* coverage = (const float*)d_in[8];
    const float* emb      = (const float*)d_in[9];
    const float* Wi       = (const float*)d_in[10];
    const float* bi       = (const float*)d_in[11];
    const float* W_ih     = (const float*)d_in[12];
    const float* W_hh     = (const float*)d_in[13];
    const float* b_ih     = (const float*)d_in[14];
    const float* b_hh     = (const float*)d_in[15];
    const float* att_wh   = (const float*)d_in[16];
    const float* att_ws   = (const float*)d_in[17];
    const float* att_wc   = (const float*)d_in[18];
    const float* att_bc   = (const float*)d_in[19];
    const float* att_v    = (const float*)d_in[20];
    const float* gp_wh    = (const float*)d_in[21];
    const float* gp_bh    = (const float*)d_in[22];
    const float* gp_ws    = (const float*)d_in[23];
    const float* gp_bs    = (const float*)d_in[24];
    const float* gp_wx    = (const float*)d_in[25];
    const float* gp_bx    = (const float*)d_in[26];
    const float* out_w1   = (const float*)d_in[27];
    const float* out_b1   = (const float*)d_in[28];
    const float* out_w2   = (const float*)d_in[29];
    const float* out_b2   = (const float*)d_in[30];
    float* out = (float*)d_out;

    k1_lstm<<<B, 256>>>(idx, h0, c0, ctxv, emb, Wi, bi, W_ih, W_hh, b_ih, b_hh,
                        att_ws, att_bc, gp_ws, gp_bs, gp_wx, gp_bx, gp_bh, out);
    k2_escore<<<(B * S) / 64, 256>>>(EO, att_wh, att_wc, att_v, coverage, emask);
    k3_softmax_ctx<<<B, 512>>>(EO, coverage, gp_wh, out);
    k3b_hidden<<<B, 256>>>(out_w1, out_b1, out);
    {
        dim3 grid((V + 63) / 64, 2);
        k4_logits<<<grid, 256>>>(out_w2, out_b2);
    }
    k5a_rowstats<<<B, 256>>>();
    k5b_final<<<(B * VO + 255) / 256, 256>>>(out);
    k5c_scatter<<<(B * S + 255) / 256, 256>>>(ewo, out);
}

// round 3
// speedup vs baseline: 1.3972x; 1.3942x over previous
#include <cuda_runtime.h>
#include <math.h>

#define B 128
#define S 400
#define H 256
#define E 128
#define V 50000
#define OOV 50
#define TWOH 512
#define VO (V + OOV)

#define OFF_HT   (B * VO)
#define OFF_CT   (OFF_HT + B * H)
#define OFF_CTX  (OFF_CT + B * H)
#define OFF_AT   (OFF_CTX + B * TWOH)
#define OFF_GP   (OFF_AT + B * S)
#define OFF_COV  (OFF_GP + B)

__device__ float g_decbase[B * TWOH];
__device__ float g_gpart[B];
__device__ float g_et[B * S];
__device__ float g_hidden[B * H];
__device__ float g_logits[(size_t)B * V];
__device__ float g_rowmax[B];
__device__ float g_rowinv[B];

__device__ __forceinline__ float sigf(float x) { return 1.0f / (1.0f + expf(-x)); }

__device__ __forceinline__ float wred(float a) {
    a += __shfl_xor_sync(0xffffffffu, a, 16);
    a += __shfl_xor_sync(0xffffffffu, a, 8);
    a += __shfl_xor_sync(0xffffffffu, a, 4);
    a += __shfl_xor_sync(0xffffffffu, a, 2);
    a += __shfl_xor_sync(0xffffffffu, a, 1);
    return a;
}

__device__ __forceinline__ unsigned f2tf(float x) {
    unsigned r; asm("cvt.rna.tf32.f32 %0, %1;" : "=r"(r) : "f"(x)); return r;
}
__device__ __forceinline__ void mma8(float c[4], const unsigned a[4], unsigned b0, unsigned b1) {
    asm("mma.sync.aligned.m16n8k8.row.col.f32.tf32.tf32.f32 "
        "{%0,%1,%2,%3}, {%4,%5,%6,%7}, {%8,%9}, {%0,%1,%2,%3};"
        : "+f"(c[0]), "+f"(c[1]), "+f"(c[2]), "+f"(c[3])
        : "r"(a[0]), "r"(a[1]), "r"(a[2]), "r"(a[3]), "r"(b0), "r"(b1));
}
__device__ __forceinline__ unsigned fu(float x) { return __float_as_uint(x); }
__device__ __forceinline__ float uf(unsigned x) { return __uint_as_float(x); }

// ---------------------------------------------------------------------------
// K1: embedding + input proj + LSTM + decbase + gen_p partial. grid=(B), 256thr.
// Warp-per-output GEMVs (coalesced weight reads).
// ---------------------------------------------------------------------------
__global__ void k1_lstm(
    const int* __restrict__ idx, const float* __restrict__ h0, const float* __restrict__ c0,
    const float* __restrict__ ctxv, const float* __restrict__ emb,
    const float* __restrict__ Wi, const float* __restrict__ bi,
    const float* __restrict__ W_ih, const float* __restrict__ W_hh,
    const float* __restrict__ b_ih, const float* __restrict__ b_hh,
    const float* __restrict__ att_ws, const float* __restrict__ att_bc,
    const float* __restrict__ gp_ws, const float* __restrict__ gp_bs,
    const float* __restrict__ gp_wx, const float* __restrict__ gp_bx,
    const float* __restrict__ gp_bh,
    float* __restrict__ out)
{
    const int b = blockIdx.x;
    const int tid = threadIdx.x;
    const int w = tid >> 5, lane = tid & 31;

    __shared__ float s_in[TWOH + E];
    __shared__ float s_x[E];
    __shared__ float s_h0[H];
    __shared__ float s_gates[4 * H];
    __shared__ float s_st[TWOH];
    __shared__ float s_red[256];

    for (int k = tid; k < TWOH; k += 256) s_in[k] = ctxv[b * TWOH + k];
    if (tid < E) s_in[TWOH + tid] = emb[(size_t)idx[b] * E + tid];
    s_h0[tid] = h0[b * H + tid];
    __syncthreads();

    for (int o = w * 16; o < (w + 1) * 16; o++) {
        const float* wr = Wi + (size_t)o * (TWOH + E);
        float a = 0.f;
        for (int k = lane; k < TWOH + E; k += 32) a += wr[k] * s_in[k];
        a = wred(a);
        if (lane == 0) s_x[o] = a + bi[o];
    }
    __syncthreads();

    for (int o = w * 128; o < (w + 1) * 128; o++) {
        const float* wi_ = W_ih + (size_t)o * E;
        const float* wh_ = W_hh + (size_t)o * H;
        float a = 0.f;
        for (int k = lane; k < E; k += 32) a += wi_[k] * s_x[k];
        for (int k = lane; k < H; k += 32) a += wh_[k] * s_h0[k];
        a = wred(a);
        if (lane == 0) s_gates[o] = a + b_ih[o] + b_hh[o];
    }
    __syncthreads();

    {
        float ig = sigf(s_gates[tid]);
        float fg = sigf(s_gates[H + tid]);
        float gg = tanhf(s_gates[2 * H + tid]);
        float og = sigf(s_gates[3 * H + tid]);
        float c = fg * c0[b * H + tid] + ig * gg;
        float h = og * tanhf(c);
        out[OFF_HT + b * H + tid] = h;
        out[OFF_CT + b * H + tid] = c;
        s_st[tid] = h;
        s_st[H + tid] = c;
    }
    __syncthreads();

    for (int o = w * 64; o < (w + 1) * 64; o++) {
        const float* wr = att_ws + (size_t)o * TWOH;
        float a = 0.f;
        for (int k = lane; k < TWOH; k += 32) a += wr[k] * s_st[k];
        a = wred(a);
        if (lane == 0) g_decbase[b * TWOH + o] = a + att_bc[o];
    }

    float p = 0.f;
    for (int k = tid; k < TWOH; k += 256) p += gp_ws[k] * s_st[k];
    if (tid < E) p += gp_wx[tid] * s_x[tid];
    s_red[tid] = p;
    __syncthreads();
    for (int off = 128; off > 0; off >>= 1) {
        if (tid < off) s_red[tid] += s_red[tid + off];
        __syncthreads();
    }
    if (tid == 0) g_gpart[b] = s_red[0] + gp_bs[0] + gp_bx[0] + gp_bh[0];
}

// ---------------------------------------------------------------------------
// K2: fused attention scores via tf32 mma (hi/lo split, 3 products).
// Block: 64 rows x 512 j, K=512 in chunks of 32. 512 threads = 16 warps (2m x 8n).
// grid=(800), dynamic smem.
// ---------------------------------------------------------------------------
#define K2_AS_LO 2304
#define K2_BS_LO 18432
#define K2_SMEM ((4608 + 36864 + 512 + 512 + 1024 + 512) * 4)

__global__ void __launch_bounds__(512, 1) k2_tc(
    const float* __restrict__ EO, const float* __restrict__ Wh,
    const float* __restrict__ att_wc, const float* __restrict__ att_v,
    const float* __restrict__ coverage, const int* __restrict__ mask)
{
    extern __shared__ float sm[];
    float* As = sm;                       // [64][36] hi, +K2_AS_LO lo
    float* Bs = sm + 4608;                // [512][36] hi, +K2_BS_LO lo
    float* sv = sm + 4608 + 36864;        // 512
    float* swc = sv + 512;                // 512
    float* sdb = swc + 512;               // [2][512]
    float* epart = sdb + 1024;            // [64][8]

    const int tid = threadIdx.x;
    const int w = tid >> 5, lane = tid & 31;
    const int g = lane >> 2, tg = lane & 3;
    const int wm = w & 1, wn = w >> 1;
    const int row0 = blockIdx.x * 64;
    const int bb0 = row0 / S;
    const int b1 = (row0 + 63) / S;

    sv[tid] = att_v[tid];
    swc[tid] = att_wc[tid];
    sdb[tid] = g_decbase[bb0 * TWOH + tid];
    sdb[512 + tid] = g_decbase[b1 * TWOH + tid];

    float c[2][8][4];
    #pragma unroll
    for (int mi = 0; mi < 2; mi++)
        #pragma unroll
        for (int ni = 0; ni < 8; ni++)
            #pragma unroll
            for (int q = 0; q < 4; q++) c[mi][ni][q] = 0.f;

    for (int kt = 0; kt < 16; kt++) {
        const int k0 = kt * 32;
        __syncthreads();
        {
            int m = tid >> 3, kq = tid & 7;
            float4 v = *(const float4*)(EO + (size_t)(row0 + m) * TWOH + k0 + kq * 4);
            float* pa = As + m * 36 + kq * 4;
            float hx = uf(f2tf(v.x)), hy = uf(f2tf(v.y)), hz = uf(f2tf(v.z)), hw = uf(f2tf(v.w));
            pa[0] = hx; pa[1] = hy; pa[2] = hz; pa[3] = hw;
            float* pl = pa + K2_AS_LO;
            pl[0] = uf(f2tf(v.x - hx)); pl[1] = uf(f2tf(v.y - hy));
            pl[2] = uf(f2tf(v.z - hz)); pl[3] = uf(f2tf(v.w - hw));
        }
        #pragma unroll
        for (int it = 0; it < 8; it++) {
            int f = it * 512 + tid;
            int n = f >> 3, kq = f & 7;
            float4 v = *(const float4*)(Wh + (size_t)n * TWOH + k0 + kq * 4);
            float* pb = Bs + n * 36 + kq * 4;
            float hx = uf(f2tf(v.x)), hy = uf(f2tf(v.y)), hz = uf(f2tf(v.z)), hw = uf(f2tf(v.w));
            pb[0] = hx; pb[1] = hy; pb[2] = hz; pb[3] = hw;
            float* pl = pb + K2_BS_LO;
            pl[0] = uf(f2tf(v.x - hx)); pl[1] = uf(f2tf(v.y - hy));
            pl[2] = uf(f2tf(v.z - hz)); pl[3] = uf(f2tf(v.w - hw));
        }
        __syncthreads();

        #pragma unroll
        for (int s = 0; s < 4; s++) {
            unsigned ah[2][4], al[2][4];
            #pragma unroll
            for (int mi = 0; mi < 2; mi++) {
                const float* p0 = As + (wm * 32 + mi * 16 + g) * 36 + s * 8 + tg;
                const float* p1 = p0 + 8 * 36;
                ah[mi][0] = fu(p0[0]); ah[mi][1] = fu(p1[0]);
                ah[mi][2] = fu(p0[4]); ah[mi][3] = fu(p1[4]);
                al[mi][0] = fu(p0[K2_AS_LO]); al[mi][1] = fu(p1[K2_AS_LO]);
                al[mi][2] = fu(p0[K2_AS_LO + 4]); al[mi][3] = fu(p1[K2_AS_LO + 4]);
            }
            #pragma unroll
            for (int ni = 0; ni < 8; ni++) {
                const float* q0 = Bs + (wn * 64 + ni * 8 + g) * 36 + s * 8 + tg;
                unsigned bh0 = fu(q0[0]), bh1 = fu(q0[4]);
                unsigned bl0 = fu(q0[K2_BS_LO]), bl1 = fu(q0[K2_BS_LO + 4]);
                #pragma unroll
                for (int mi = 0; mi < 2; mi++) {
                    mma8(c[mi][ni], ah[mi], bh0, bh1);
                    mma8(c[mi][ni], al[mi], bh0, bh1);
                    mma8(c[mi][ni], ah[mi], bl0, bl1);
                }
            }
        }
    }

    // epilogue: exact tanh + v-dot, then cross-warp reduce
    #pragma unroll
    for (int mi = 0; mi < 2; mi++) {
        #pragma unroll
        for (int hf = 0; hf < 2; hf++) {
            const int rl = wm * 32 + mi * 16 + hf * 8 + g;
            const int r = row0 + rl;
            const int dbo = (r / S != bb0) ? 512 : 0;
            const float cov = coverage[r];
            float acc = 0.f;
            #pragma unroll
            for (int ni = 0; ni < 8; ni++) {
                const int j = wn * 64 + ni * 8 + tg * 2;
                float v0 = c[mi][ni][hf * 2 + 0] + sdb[dbo + j] + cov * swc[j];
                float v1 = c[mi][ni][hf * 2 + 1] + sdb[dbo + j + 1] + cov * swc[j + 1];
                acc += sv[j] * tanhf(v0) + sv[j + 1] * tanhf(v1);
            }
            acc += __shfl_xor_sync(0xffffffffu, acc, 1);
            acc += __shfl_xor_sync(0xffffffffu, acc, 2);
            if (tg == 0) epart[rl * 8 + wn] = acc;
        }
    }
    __syncthreads();
    if (tid < 64) {
        float sacc = 0.f;
        #pragma unroll
        for (int t2 = 0; t2 < 8; t2++) sacc += epart[tid * 8 + t2];
        const int r = row0 + tid;
        g_et[r] = (mask[r] == 0) ? -1e30f : sacc;
    }
}

// ---------------------------------------------------------------------------
// K3: masked softmax over S, a_t, next_coverage, ctx, gen_p. grid=(B), 512thr.
// ---------------------------------------------------------------------------
__global__ void k3_softmax_ctx(
    const float* __restrict__ EO, const float* __restrict__ coverage,
    const float* __restrict__ gp_wh, float* __restrict__ out)
{
    const int b = blockIdx.x;
    const int t = threadIdx.x;

    __shared__ float sa[S];
    __shared__ float red[512];

    float e = (t < S) ? g_et[b * S + t] : -1e30f;
    red[t] = e;
    __syncthreads();
    for (int off = 256; off > 0; off >>= 1) {
        if (t < off) red[t] = fmaxf(red[t], red[t + off]);
        __syncthreads();
    }
    const float mx = red[0];
    __syncthreads();

    float ex = (t < S) ? expf(e - mx) : 0.f;
    red[t] = ex;
    __syncthreads();
    for (int off = 256; off > 0; off >>= 1) {
        if (t < off) red[t] += red[t + off];
        __syncthreads();
    }
    const float inv = 1.f / red[0];
    __syncthreads();

    if (t < S) {
        float a = ex * inv;
        sa[t] = a;
        out[OFF_AT + b * S + t] = a;
        out[OFF_COV + b * S + t] = coverage[b * S + t] + a;
    }
    __syncthreads();

    const float* eob = EO + (size_t)b * S * TWOH;
    float c = 0.f;
    #pragma unroll 8
    for (int s = 0; s < S; s++) c += sa[s] * eob[(size_t)s * TWOH + t];
    out[OFF_CTX + b * TWOH + t] = c;

    red[t] = gp_wh[t] * c;
    __syncthreads();
    for (int off = 256; off > 0; off >>= 1) {
        if (t < off) red[t] += red[t + off];
        __syncthreads();
    }
    if (t == 0) out[OFF_GP + b] = sigf(red[0] + g_gpart[b]);
}

// ---------------------------------------------------------------------------
// K3b: hidden = relu(out_w1 @ [h_t, ctx] + b1). Warp-per-output. grid=(4096),256thr.
// ---------------------------------------------------------------------------
__global__ void k3b_hidden(
    const float* __restrict__ out_w1, const float* __restrict__ out_b1,
    const float* __restrict__ out)
{
    const int gw = blockIdx.x * 8 + (threadIdx.x >> 5);
    const int lane = threadIdx.x & 31;
    const int b = gw >> 8, o = gw & 255;
    const float* wr = out_w1 + (size_t)o * (H + TWOH);
    const float* fh = out + OFF_HT + b * H;
    const float* fc = out + OFF_CTX + b * TWOH;
    float a = 0.f;
    for (int k = lane; k < H; k += 32) a += wr[k] * fh[k];
    for (int k = lane; k < TWOH; k += 32) a += wr[H + k] * fc[k];
    a = wred(a);
    if (lane == 0) g_hidden[b * H + o] = fmaxf(a + out_b1[o], 0.f);
}

// ---------------------------------------------------------------------------
// K4: logits = hidden @ out_w2.T + b2 via tf32 split. 128 rows x 256 n per block.
// 512 threads = 16 warps (4m x 4n). grid=(196).
// ---------------------------------------------------------------------------
#define K4_AS_LO 4608
#define K4_BS_LO 9216
#define K4_SMEM ((9216 + 18432) * 4)

__global__ void __launch_bounds__(512, 1) k4_tc(
    const float* __restrict__ W2, const float* __restrict__ b2)
{
    extern __shared__ float sm[];
    float* As = sm;           // [128][36] hi, +K4_AS_LO lo
    float* Bs = sm + 9216;    // [256][36] hi, +K4_BS_LO lo

    const int tid = threadIdx.x;
    const int w = tid >> 5, lane = tid & 31;
    const int g = lane >> 2, tg = lane & 3;
    const int wm = w & 3, wn = w >> 2;
    const int j0 = blockIdx.x * 256;

    float c[2][8][4];
    #pragma unroll
    for (int mi = 0; mi < 2; mi++)
        #pragma unroll
        for (int ni = 0; ni < 8; ni++)
            #pragma unroll
            for (int q = 0; q < 4; q++) c[mi][ni][q] = 0.f;

    for (int kt = 0; kt < 8; kt++) {
        const int k0 = kt * 32;
        __syncthreads();
        #pragma unroll
        for (int it = 0; it < 2; it++) {
            int f = it * 512 + tid;
            int m = f >> 3, kq = f & 7;
            float4 v = *(const float4*)(g_hidden + (size_t)m * H + k0 + kq * 4);
            float* pa = As + m * 36 + kq * 4;
            float hx = uf(f2tf(v.x)), hy = uf(f2tf(v.y)), hz = uf(f2tf(v.z)), hw = uf(f2tf(v.w));
            pa[0] = hx; pa[1] = hy; pa[2] = hz; pa[3] = hw;
            float* pl = pa + K4_AS_LO;
            pl[0] = uf(f2tf(v.x - hx)); pl[1] = uf(f2tf(v.y - hy));
            pl[2] = uf(f2tf(v.z - hz)); pl[3] = uf(f2tf(v.w - hw));
        }
        #pragma unroll
        for (int it = 0; it < 4; it++) {
            int f = it * 512 + tid;
            int n = f >> 3, kq = f & 7;
            int j = j0 + n;
            float4 v = make_float4(0.f, 0.f, 0.f, 0.f);
            if (j < V) v = *(const float4*)(W2 + (size_t)j * H + k0 + kq * 4);
            float* pb = Bs + n * 36 + kq * 4;
            float hx = uf(f2tf(v.x)), hy = uf(f2tf(v.y)), hz = uf(f2tf(v.z)), hw = uf(f2tf(v.w));
            pb[0] = hx; pb[1] = hy; pb[2] = hz; pb[3] = hw;
            float* pl = pb + K4_BS_LO;
            pl[0] = uf(f2tf(v.x - hx)); pl[1] = uf(f2tf(v.y - hy));
            pl[2] = uf(f2tf(v.z - hz)); pl[3] = uf(f2tf(v.w - hw));
        }
        __syncthreads();

        #pragma unroll
        for (int s = 0; s < 4; s++) {
            unsigned ah[2][4], al[2][4];
            #pragma unroll
            for (int mi = 0; mi < 2; mi++) {
                const float* p0 = As + (wm * 32 + mi * 16 + g) * 36 + s * 8 + tg;
                const float* p1 = p0 + 8 * 36;
                ah[mi][0] = fu(p0[0]); ah[mi][1] = fu(p1[0]);
                ah[mi][2] = fu(p0[4]); ah[mi][3] = fu(p1[4]);
                al[mi][0] = fu(p0[K4_AS_LO]); al[mi][1] = fu(p1[K4_AS_LO]);
                al[mi][2] = fu(p0[K4_AS_LO + 4]); al[mi][3] = fu(p1[K4_AS_LO + 4]);
            }
            #pragma unroll
            for (int ni = 0; ni < 8; ni++) {
                const float* q0 = Bs + (wn * 64 + ni * 8 + g) * 36 + s * 8 + tg;
                unsigned bh0 = fu(q0[0]), bh1 = fu(q0[4]);
                unsigned bl0 = fu(q0[K4_BS_LO]), bl1 = fu(q0[K4_BS_LO + 4]);
                #pragma unroll
                for (int mi = 0; mi < 2; mi++) {
                    mma8(c[mi][ni], ah[mi], bh0, bh1);
                    mma8(c[mi][ni], al[mi], bh0, bh1);
                    mma8(c[mi][ni], ah[mi], bl0, bl1);
                }
            }
        }
    }

    #pragma unroll
    for (int mi = 0; mi < 2; mi++) {
        #pragma unroll
        for (int hf = 0; hf < 2; hf++) {
            const int r = wm * 32 + mi * 16 + hf * 8 + g;
            #pragma unroll
            for (int ni = 0; ni < 8; ni++) {
                const int j = j0 + wn * 64 + ni * 8 + tg * 2;
                if (j < V) {
                    float2 o2;
                    o2.x = c[mi][ni][hf * 2 + 0] + b2[j];
                    o2.y = c[mi][ni][hf * 2 + 1] + b2[j + 1];
                    *(float2*)(g_logits + (size_t)r * V + j) = o2;
                }
            }
        }
    }
}

// ---------------------------------------------------------------------------
// K5a: per-row max & inv-sumexp. grid=(B), 256thr.
// ---------------------------------------------------------------------------
__global__ void k5a_rowstats()
{
    const int b = blockIdx.x, t = threadIdx.x;
    __shared__ float red[256];
    const float* lr = g_logits + (size_t)b * V;

    float mx = -1e30f;
    for (int j = t; j < V; j += 256) mx = fmaxf(mx, lr[j]);
    red[t] = mx;
    __syncthreads();
    for (int off = 128; off > 0; off >>= 1) {
        if (t < off) red[t] = fmaxf(red[t], red[t + off]);
        __syncthreads();
    }
    mx = red[0];
    __syncthreads();

    float s = 0.f;
    for (int j = t; j < V; j += 256) s += expf(lr[j] - mx);
    red[t] = s;
    __syncthreads();
    for (int off = 128; off > 0; off >>= 1) {
        if (t < off) red[t] += red[t + off];
        __syncthreads();
    }
    if (t == 0) { g_rowmax[b] = mx; g_rowinv[b] = 1.f / red[0]; }
}

// ---------------------------------------------------------------------------
// K5b: final_dist = softmax(logits)*gen_p, zero OOV tail.
// ---------------------------------------------------------------------------
__global__ void k5b_final(float* __restrict__ out)
{
    const int i = blockIdx.x * 256 + threadIdx.x;
    if (i >= B * VO) return;
    const int b = i / VO;
    const int c = i - b * VO;
    float v = 0.f;
    if (c < V) {
        const float gp = out[OFF_GP + b];
        v = expf(g_logits[(size_t)b * V + c] - g_rowmax[b]) * g_rowinv[b] * gp;
    }
    out[i] = v;
}

// ---------------------------------------------------------------------------
// K5c: scatter-add a_t*(1-gen_p) at encoder_with_oov.
// ---------------------------------------------------------------------------
__global__ void k5c_scatter(const int* __restrict__ ewo, float* __restrict__ out)
{
    const int i = blockIdx.x * 256 + threadIdx.x;
    if (i >= B * S) return;
    const int b = i / S;
    const float gp = out[OFF_GP + b];
    const float a = out[OFF_AT + i];
    atomicAdd(out + (size_t)b * VO + ewo[i], a * (1.f - gp));
}

// ---------------------------------------------------------------------------
extern "C" void kernel_launch(void* const* d_in, const int* in_sizes, int n_in,
                              void* d_out, int out_size)
{
    const int*   idx      = (const int*)  d_in[0];
    const float* h0       = (const float*)d_in[1];
    const float* c0       = (const float*)d_in[2];
    const float* EO       = (const float*)d_in[3];
    const int*   emask    = (const int*)  d_in[4];
    const float* ctxv     = (const float*)d_in[5];
    const int*   ewo      = (const int*)  d_in[7];
    const float* coverage = (const float*)d_in[8];
    const float* emb      = (const float*)d_in[9];
    const float* Wi       = (const float*)d_in[10];
    const float* bi       = (const float*)d_in[11];
    const float* W_ih     = (const float*)d_in[12];
    const float* W_hh     = (const float*)d_in[13];
    const float* b_ih     = (const float*)d_in[14];
    const float* b_hh     = (const float*)d_in[15];
    const float* att_wh   = (const float*)d_in[16];
    const float* att_ws   = (const float*)d_in[17];
    const float* att_wc   = (const float*)d_in[18];
    const float* att_bc   = (const float*)d_in[19];
    const float* att_v    = (const float*)d_in[20];
    const float* gp_wh    = (const float*)d_in[21];
    const float* gp_bh    = (const float*)d_in[22];
    const float* gp_ws    = (const float*)d_in[23];
    const float* gp_bs    = (const float*)d_in[24];
    const float* gp_wx    = (const float*)d_in[25];
    const float* gp_bx    = (const float*)d_in[26];
    const float* out_w1   = (const float*)d_in[27];
    const float* out_b1   = (const float*)d_in[28];
    const float* out_w2   = (const float*)d_in[29];
    const float* out_b2   = (const float*)d_in[30];
    float* out = (float*)d_out;

    static int attr_done = 0;
    if (!attr_done) {
        cudaFuncSetAttribute(k2_tc, cudaFuncAttributeMaxDynamicSharedMemorySize, K2_SMEM);
        cudaFuncSetAttribute(k4_tc, cudaFuncAttributeMaxDynamicSharedMemorySize, K4_SMEM);
        attr_done = 1;
    }

    k1_lstm<<<B, 256>>>(idx, h0, c0, ctxv, emb, Wi, bi, W_ih, W_hh, b_ih, b_hh,
                        att_ws, att_bc, gp_ws, gp_bs, gp_wx, gp_bx, gp_bh, out);
    k2_tc<<<(B * S) / 64, 512, K2_SMEM>>>(EO, att_wh, att_wc, att_v, coverage, emask);
    k3_softmax_ctx<<<B, 512>>>(EO, coverage, gp_wh, out);
    k3b_hidden<<<(B * H) / 8, 256>>>(out_w1, out_b1, out);
    k4_tc<<<(V + 255) / 256, 512, K4_SMEM>>>(out_w2, out_b2);
    k5a_rowstats<<<B, 256>>>();
    k5b_final<<<(B * VO + 255) / 256, 256>>>(out);
    k5c_scatter<<<(B * S + 255) / 256, 256>>>(ewo, out);
}

// round 5
// speedup vs baseline: 1.7322x; 1.2398x over previous
#include <cuda_runtime.h>
#include <cuda_fp16.h>
#include <math.h>

#define B 128
#define S 400
#define H 256
#define E 128
#define V 50000
#define OOV 50
#define TWOH 512
#define VO (V + OOV)

#define OFF_HT   (B * VO)
#define OFF_CT   (OFF_HT + B * H)
#define OFF_CTX  (OFF_CT + B * H)
#define OFF_AT   (OFF_CTX + B * TWOH)
#define OFF_GP   (OFF_AT + B * S)
#define OFF_COV  (OFF_GP + B)

__device__ float g_decbase[B * TWOH];
__device__ float g_gpart[B];
__device__ float g_et[B * S];
__device__ float g_hidden[B * H];
__device__ float g_logits[(size_t)B * V];
__device__ float g_rowmax[B];
__device__ float g_rowinv[B];
__device__ float g_pmax[B * 25];
__device__ float g_psum[B * 25];
// Wh pre-split into fp16 hi/lo, k-pair packed, chunked: [16 chunks][512 n][16 kp]
__device__ unsigned g_WhHi[16 * 512 * 16];
__device__ unsigned g_WhLo[16 * 512 * 16];

__device__ __forceinline__ float sigf(float x) { return 1.0f / (1.0f + expf(-x)); }

__device__ __forceinline__ float wred(float a) {
    a += __shfl_xor_sync(0xffffffffu, a, 16);
    a += __shfl_xor_sync(0xffffffffu, a, 8);
    a += __shfl_xor_sync(0xffffffffu, a, 4);
    a += __shfl_xor_sync(0xffffffffu, a, 2);
    a += __shfl_xor_sync(0xffffffffu, a, 1);
    return a;
}

__device__ __forceinline__ void splitpack(float x, float y, unsigned& hi, unsigned& lo) {
    __half hx = __float2half_rn(x), hy = __float2half_rn(y);
    __half lx = __float2half_rn(x - __half2float(hx));
    __half ly = __float2half_rn(y - __half2float(hy));
    hi = ((unsigned)__half_as_ushort(hy) << 16) | (unsigned)__half_as_ushort(hx);
    lo = ((unsigned)__half_as_ushort(ly) << 16) | (unsigned)__half_as_ushort(lx);
}

// fp16 m16n8k16 mma, fp32 accumulate
__device__ __forceinline__ void mma16(float c[4], const unsigned a[4], unsigned b0, unsigned b1) {
    asm("mma.sync.aligned.m16n8k16.row.col.f32.f16.f16.f32 "
        "{%0,%1,%2,%3}, {%4,%5,%6,%7}, {%8,%9}, {%0,%1,%2,%3};"
        : "+f"(c[0]), "+f"(c[1]), "+f"(c[2]), "+f"(c[3])
        : "r"(a[0]), "r"(a[1]), "r"(a[2]), "r"(a[3]), "r"(b0), "r"(b1));
}

// ---------------------------------------------------------------------------
// K0: pre-split Wh into fp16 hi/lo packed pairs. grid=(512), 256thr.
// ---------------------------------------------------------------------------
__global__ void k0_wh(const float* __restrict__ Wh)
{
    int idx = blockIdx.x * 256 + threadIdx.x;    // 131072 pairs
    int n = idx >> 8;                             // 0..511
    int kpg = idx & 255;                          // global kpair
    int k = kpg * 2;
    int c = k >> 5, kp = (k & 31) >> 1;
    float2 v = *(const float2*)(Wh + (size_t)n * TWOH + k);
    unsigned hi, lo;
    splitpack(v.x, v.y, hi, lo);
    int d = (c * 512 + n) * 16 + kp;
    g_WhHi[d] = hi;
    g_WhLo[d] = lo;
}

// ---------------------------------------------------------------------------
// K1: embedding + input proj + LSTM + decbase + gen_p partial. grid=(B), 256thr.
// ---------------------------------------------------------------------------
__global__ void k1_lstm(
    const int* __restrict__ idx, const float* __restrict__ h0, const float* __restrict__ c0,
    const float* __restrict__ ctxv, const float* __restrict__ emb,
    const float* __restrict__ Wi, const float* __restrict__ bi,
    const float* __restrict__ W_ih, const float* __restrict__ W_hh,
    const float* __restrict__ b_ih, const float* __restrict__ b_hh,
    const float* __restrict__ att_ws, const float* __restrict__ att_bc,
    const float* __restrict__ gp_ws, const float* __restrict__ gp_bs,
    const float* __restrict__ gp_wx, const float* __restrict__ gp_bx,
    const float* __restrict__ gp_bh,
    float* __restrict__ out)
{
    const int b = blockIdx.x;
    const int tid = threadIdx.x;
    const int w = tid >> 5, lane = tid & 31;

    __shared__ float s_in[TWOH + E];
    __shared__ float s_x[E];
    __shared__ float s_h0[H];
    __shared__ float s_gates[4 * H];
    __shared__ float s_st[TWOH];
    __shared__ float s_red[256];

    for (int k = tid; k < TWOH; k += 256) s_in[k] = ctxv[b * TWOH + k];
    if (tid < E) s_in[TWOH + tid] = emb[(size_t)idx[b] * E + tid];
    s_h0[tid] = h0[b * H + tid];
    __syncthreads();

    for (int o = w * 16; o < (w + 1) * 16; o++) {
        const float* wr = Wi + (size_t)o * (TWOH + E);
        float a = 0.f;
        for (int k = lane; k < TWOH + E; k += 32) a += wr[k] * s_in[k];
        a = wred(a);
        if (lane == 0) s_x[o] = a + bi[o];
    }
    __syncthreads();

    for (int o = w * 128; o < (w + 1) * 128; o++) {
        const float* wi_ = W_ih + (size_t)o * E;
        const float* wh_ = W_hh + (size_t)o * H;
        float a = 0.f;
        for (int k = lane; k < E; k += 32) a += wi_[k] * s_x[k];
        for (int k = lane; k < H; k += 32) a += wh_[k] * s_h0[k];
        a = wred(a);
        if (lane == 0) s_gates[o] = a + b_ih[o] + b_hh[o];
    }
    __syncthreads();

    {
        float ig = sigf(s_gates[tid]);
        float fg = sigf(s_gates[H + tid]);
        float gg = tanhf(s_gates[2 * H + tid]);
        float og = sigf(s_gates[3 * H + tid]);
        float c = fg * c0[b * H + tid] + ig * gg;
        float h = og * tanhf(c);
        out[OFF_HT + b * H + tid] = h;
        out[OFF_CT + b * H + tid] = c;
        s_st[tid] = h;
        s_st[H + tid] = c;
    }
    __syncthreads();

    for (int o = w * 64; o < (w + 1) * 64; o++) {
        const float* wr = att_ws + (size_t)o * TWOH;
        float a = 0.f;
        for (int k = lane; k < TWOH; k += 32) a += wr[k] * s_st[k];
        a = wred(a);
        if (lane == 0) g_decbase[b * TWOH + o] = a + att_bc[o];
    }

    float p = 0.f;
    for (int k = tid; k < TWOH; k += 256) p += gp_ws[k] * s_st[k];
    if (tid < E) p += gp_wx[tid] * s_x[tid];
    s_red[tid] = p;
    __syncthreads();
    for (int off = 128; off > 0; off >>= 1) {
        if (tid < off) s_red[tid] += s_red[tid + off];
        __syncthreads();
    }
    if (tid == 0) g_gpart[b] = s_red[0] + gp_bs[0] + gp_bx[0] + gp_bh[0];
}

// ---------------------------------------------------------------------------
// K2: attention scores via fp16 mma m16n8k16, hi/lo split, 3 products.
// Block: 64 rows x 512 n, K=512 in 16 chunks of 32. 512thr = 16 warps (2m x 8n).
// Frags load straight from k-pair-packed smem (pitch 20, conflict-free).
// ---------------------------------------------------------------------------
#define K2P 20
#define K2_AH 0
#define K2_AL 5120
#define K2_BH 10240
#define K2_BL 51200
#define K2_SV 92160
#define K2_SWC 94208
#define K2_SDB 96256
#define K2_EP 100352
#define K2_SMEM 102400

__global__ void __launch_bounds__(512, 1) k2_mma(
    const float* __restrict__ EO,
    const float* __restrict__ att_wc, const float* __restrict__ att_v,
    const float* __restrict__ coverage, const int* __restrict__ mask)
{
    extern __shared__ char smem[];
    unsigned* AHp = (unsigned*)(smem + K2_AH);
    unsigned* ALp = (unsigned*)(smem + K2_AL);
    unsigned* BHp = (unsigned*)(smem + K2_BH);
    unsigned* BLp = (unsigned*)(smem + K2_BL);
    float* sv  = (float*)(smem + K2_SV);
    float* swc = (float*)(smem + K2_SWC);
    float* sdb = (float*)(smem + K2_SDB);
    float* ep  = (float*)(smem + K2_EP);

    const int tid = threadIdx.x;
    const int w = tid >> 5, lane = tid & 31;
    const int g = lane >> 2, t = lane & 3;
    const int wm = w & 1, wn = w >> 1;
    const int row0 = blockIdx.x * 64;
    const int b0 = row0 / S;
    const int b1e = (row0 + 63) / S;

    if (tid < 512) {
        sv[tid] = att_v[tid];
        swc[tid] = att_wc[tid];
        sdb[tid] = g_decbase[b0 * TWOH + tid];
        sdb[512 + tid] = g_decbase[b1e * TWOH + tid];
    }

    float c[2][8][4];
    #pragma unroll
    for (int mi = 0; mi < 2; mi++)
        #pragma unroll
        for (int ni = 0; ni < 8; ni++)
            #pragma unroll
            for (int q = 0; q < 4; q++) c[mi][ni][q] = 0.f;

    for (int kt = 0; kt < 16; kt++) {
        const int k0 = kt * 32;
        __syncthreads();
        // A tile: 64 rows x 32 k -> hi/lo packed pairs
        {
            int r = tid >> 3, q = tid & 7;
            float4 v = *(const float4*)(EO + (size_t)(row0 + r) * TWOH + k0 + q * 4);
            unsigned h0_, l0_, h1_, l1_;
            splitpack(v.x, v.y, h0_, l0_);
            splitpack(v.z, v.w, h1_, l1_);
            uint2* pah = (uint2*)(AHp + r * K2P + q * 2);
            uint2* pal = (uint2*)(ALp + r * K2P + q * 2);
            *pah = make_uint2(h0_, h1_);
            *pal = make_uint2(l0_, l1_);
        }
        // B tile: 512 rows x 32 k from precomputed packed arrays
        #pragma unroll
        for (int i = 0; i < 4; i++) {
            int f = i * 512 + tid;
            int n = f >> 2, kq = f & 3;
            const uint4* srcH = (const uint4*)(g_WhHi + ((kt * 512 + n) * 16 + kq * 4));
            const uint4* srcL = (const uint4*)(g_WhLo + ((kt * 512 + n) * 16 + kq * 4));
            *(uint4*)(BHp + n * K2P + kq * 4) = *srcH;
            *(uint4*)(BLp + n * K2P + kq * 4) = *srcL;
        }
        __syncthreads();

        #pragma unroll
        for (int s = 0; s < 2; s++) {
            unsigned ah[2][4], al[2][4];
            #pragma unroll
            for (int mi = 0; mi < 2; mi++) {
                const unsigned* pa = AHp + (wm * 32 + mi * 16 + g) * K2P + s * 8 + t;
                ah[mi][0] = pa[0]; ah[mi][1] = pa[8 * K2P];
                ah[mi][2] = pa[4]; ah[mi][3] = pa[8 * K2P + 4];
                const unsigned* pl = ALp + (wm * 32 + mi * 16 + g) * K2P + s * 8 + t;
                al[mi][0] = pl[0]; al[mi][1] = pl[8 * K2P];
                al[mi][2] = pl[4]; al[mi][3] = pl[8 * K2P + 4];
            }
            #pragma unroll
            for (int ni = 0; ni < 8; ni++) {
                const unsigned* pb = BHp + (wn * 64 + ni * 8 + g) * K2P + s * 8 + t;
                unsigned bh0 = pb[0], bh1 = pb[4];
                const unsigned* pbl = BLp + (wn * 64 + ni * 8 + g) * K2P + s * 8 + t;
                unsigned bl0 = pbl[0], bl1 = pbl[4];
                #pragma unroll
                for (int mi = 0; mi < 2; mi++) {
                    mma16(c[mi][ni], ah[mi], bh0, bh1);
                    mma16(c[mi][ni], al[mi], bh0, bh1);
                    mma16(c[mi][ni], ah[mi], bl0, bl1);
                }
            }
        }
    }

    // epilogue: exact tanh + v-dot; reduce over tg, then over 8 n-warps
    #pragma unroll
    for (int mi = 0; mi < 2; mi++) {
        #pragma unroll
        for (int hf = 0; hf < 2; hf++) {
            const int rl = wm * 32 + mi * 16 + hf * 8 + g;
            const int r = row0 + rl;
            const int dbo = (r / S != b0) ? 512 : 0;
            const float cov = coverage[r];
            float acc = 0.f;
            #pragma unroll
            for (int ni = 0; ni < 8; ni++) {
                const int j = wn * 64 + ni * 8 + t * 2;
                float v0 = c[mi][ni][hf * 2 + 0] + sdb[dbo + j] + cov * swc[j];
                float v1 = c[mi][ni][hf * 2 + 1] + sdb[dbo + j + 1] + cov * swc[j + 1];
                acc += sv[j] * tanhf(v0) + sv[j + 1] * tanhf(v1);
            }
            acc += __shfl_xor_sync(0xffffffffu, acc, 1);
            acc += __shfl_xor_sync(0xffffffffu, acc, 2);
            if (t == 0) ep[rl * 8 + wn] = acc;
        }
    }
    __syncthreads();
    if (tid < 64) {
        float sacc = 0.f;
        #pragma unroll
        for (int q = 0; q < 8; q++) sacc += ep[tid * 8 + q];
        const int r = row0 + tid;
        g_et[r] = (mask[r] == 0) ? -1e30f : sacc;
    }
}

// ---------------------------------------------------------------------------
// K3: masked softmax over S, a_t, next_coverage, ctx, gen_p. grid=(B), 512thr.
// ---------------------------------------------------------------------------
__global__ void k3_softmax_ctx(
    const float* __restrict__ EO, const float* __restrict__ coverage,
    const float* __restrict__ gp_wh, float* __restrict__ out)
{
    const int b = blockIdx.x;
    const int t = threadIdx.x;

    __shared__ float sa[S];
    __shared__ float red[512];

    float e = (t < S) ? g_et[b * S + t] : -1e30f;
    red[t] = e;
    __syncthreads();
    for (int off = 256; off > 0; off >>= 1) {
        if (t < off) red[t] = fmaxf(red[t], red[t + off]);
        __syncthreads();
    }
    const float mx = red[0];
    __syncthreads();

    float ex = (t < S) ? expf(e - mx) : 0.f;
    red[t] = ex;
    __syncthreads();
    for (int off = 256; off > 0; off >>= 1) {
        if (t < off) red[t] += red[t + off];
        __syncthreads();
    }
    const float inv = 1.f / red[0];
    __syncthreads();

    if (t < S) {
        float a = ex * inv;
        sa[t] = a;
        out[OFF_AT + b * S + t] = a;
        out[OFF_COV + b * S + t] = coverage[b * S + t] + a;
    }
    __syncthreads();

    const float* eob = EO + (size_t)b * S * TWOH;
    float c = 0.f;
    #pragma unroll 8
    for (int s = 0; s < S; s++) c += sa[s] * eob[(size_t)s * TWOH + t];
    out[OFF_CTX + b * TWOH + t] = c;

    red[t] = gp_wh[t] * c;
    __syncthreads();
    for (int off = 256; off > 0; off >>= 1) {
        if (t < off) red[t] += red[t + off];
        __syncthreads();
    }
    if (t == 0) out[OFF_GP + b] = sigf(red[0] + g_gpart[b]);
}

// ---------------------------------------------------------------------------
// K3b: hidden = relu(out_w1 @ [h_t, ctx] + b1), tiled 64x64. grid=(4,2), 256thr.
// ---------------------------------------------------------------------------
__global__ void k3b_hidden(
    const float* __restrict__ out_w1, const float* __restrict__ out_b1,
    const float* __restrict__ out)
{
    __shared__ __align__(16) float As[16][68];
    __shared__ __align__(16) float Ws[16][68];

    const int tid = threadIdx.x;
    const int tx = tid & 15, ty = tid >> 4;
    const int rl = tid >> 2, kq = tid & 3;
    const int m0 = blockIdx.y * 64;
    const int n0 = blockIdx.x * 64;

    float acc[4][4];
    #pragma unroll
    for (int a = 0; a < 4; a++)
        #pragma unroll
        for (int c = 0; c < 4; c++) acc[a][c] = 0.f;

    for (int kt = 0; kt < 48; kt++) {
        const int k = kt * 16 + kq * 4;
        const int m = m0 + rl;
        float4 av = (k < H)
            ? *(const float4*)(out + OFF_HT + m * H + k)
            : *(const float4*)(out + OFF_CTX + m * TWOH + (k - H));
        float4 wv = *(const float4*)(out_w1 + (size_t)(n0 + rl) * (H + TWOH) + k);
        __syncthreads();
        As[kq * 4 + 0][rl] = av.x; As[kq * 4 + 1][rl] = av.y;
        As[kq * 4 + 2][rl] = av.z; As[kq * 4 + 3][rl] = av.w;
        Ws[kq * 4 + 0][rl] = wv.x; Ws[kq * 4 + 1][rl] = wv.y;
        Ws[kq * 4 + 2][rl] = wv.z; Ws[kq * 4 + 3][rl] = wv.w;
        __syncthreads();
        #pragma unroll
        for (int kk = 0; kk < 16; kk++) {
            float ar[4], wr[4];
            *(float4*)ar = *(const float4*)&As[kk][ty * 4];
            *(float4*)wr = *(const float4*)&Ws[kk][tx * 4];
            #pragma unroll
            for (int mi = 0; mi < 4; mi++)
                #pragma unroll
                for (int jj = 0; jj < 4; jj++)
                    acc[mi][jj] += ar[mi] * wr[jj];
        }
    }

    #pragma unroll
    for (int mi = 0; mi < 4; mi++) {
        const int m = m0 + ty * 4 + mi;
        #pragma unroll
        for (int jj = 0; jj < 4; jj++) {
            const int o = n0 + tx * 4 + jj;
            g_hidden[m * H + o] = fmaxf(acc[mi][jj] + out_b1[o], 0.f);
        }
    }
}

// ---------------------------------------------------------------------------
// K4: logits = hidden @ out_w2.T + b2, fp16 3-product mma.
// Block 128m x 256n, K=256 (8 chunks of 32). 512thr = 16 warps (4m x 4n).
// ---------------------------------------------------------------------------
#define K4_AH 0
#define K4_AL 10240
#define K4_BH 20480
#define K4_BL 40960
#define K4_SMEM 61440

__global__ void __launch_bounds__(512, 1) k4_mma(
    const float* __restrict__ W2, const float* __restrict__ b2)
{
    extern __shared__ char smem[];
    unsigned* AHp = (unsigned*)(smem + K4_AH);
    unsigned* ALp = (unsigned*)(smem + K4_AL);
    unsigned* BHp = (unsigned*)(smem + K4_BH);
    unsigned* BLp = (unsigned*)(smem + K4_BL);

    const int tid = threadIdx.x;
    const int w = tid >> 5, lane = tid & 31;
    const int g = lane >> 2, t = lane & 3;
    const int wm = w & 3, wn = w >> 2;
    const int j0 = blockIdx.x * 256;

    float c[2][8][4];
    #pragma unroll
    for (int mi = 0; mi < 2; mi++)
        #pragma unroll
        for (int ni = 0; ni < 8; ni++)
            #pragma unroll
            for (int q = 0; q < 4; q++) c[mi][ni][q] = 0.f;

    for (int kt = 0; kt < 8; kt++) {
        const int k0 = kt * 32;
        __syncthreads();
        // A: g_hidden 128 x 32
        #pragma unroll
        for (int i = 0; i < 2; i++) {
            int f = i * 512 + tid;
            int r = f >> 3, q = f & 7;
            float4 v = *(const float4*)(g_hidden + (size_t)r * H + k0 + q * 4);
            unsigned h0_, l0_, h1_, l1_;
            splitpack(v.x, v.y, h0_, l0_);
            splitpack(v.z, v.w, h1_, l1_);
            *(uint2*)(AHp + r * K2P + q * 2) = make_uint2(h0_, h1_);
            *(uint2*)(ALp + r * K2P + q * 2) = make_uint2(l0_, l1_);
        }
        // B: W2 rows j0..j0+255 x 32
        #pragma unroll
        for (int i = 0; i < 4; i++) {
            int f = i * 512 + tid;
            int n = f >> 3, q = f & 7;
            int j = j0 + n;
            float4 v = make_float4(0.f, 0.f, 0.f, 0.f);
            if (j < V) v = *(const float4*)(W2 + (size_t)j * H + k0 + q * 4);
            unsigned h0_, l0_, h1_, l1_;
            splitpack(v.x, v.y, h0_, l0_);
            splitpack(v.z, v.w, h1_, l1_);
            *(uint2*)(BHp + n * K2P + q * 2) = make_uint2(h0_, h1_);
            *(uint2*)(BLp + n * K2P + q * 2) = make_uint2(l0_, l1_);
        }
        __syncthreads();

        #pragma unroll
        for (int s = 0; s < 2; s++) {
            unsigned ah[2][4], al[2][4];
            #pragma unroll
            for (int mi = 0; mi < 2; mi++) {
                const unsigned* pa = AHp + (wm * 32 + mi * 16 + g) * K2P + s * 8 + t;
                ah[mi][0] = pa[0]; ah[mi][1] = pa[8 * K2P];
                ah[mi][2] = pa[4]; ah[mi][3] = pa[8 * K2P + 4];
                const unsigned* pl = ALp + (wm * 32 + mi * 16 + g) * K2P + s * 8 + t;
                al[mi][0] = pl[0]; al[mi][1] = pl[8 * K2P];
                al[mi][2] = pl[4]; al[mi][3] = pl[8 * K2P + 4];
            }
            #pragma unroll
            for (int ni = 0; ni < 8; ni++) {
                const unsigned* pb = BHp + (wn * 64 + ni * 8 + g) * K2P + s * 8 + t;
                unsigned bh0 = pb[0], bh1 = pb[4];
                const unsigned* pbl = BLp + (wn * 64 + ni * 8 + g) * K2P + s * 8 + t;
                unsigned bl0 = pbl[0], bl1 = pbl[4];
                #pragma unroll
                for (int mi = 0; mi < 2; mi++) {
                    mma16(c[mi][ni], ah[mi], bh0, bh1);
                    mma16(c[mi][ni], al[mi], bh0, bh1);
                    mma16(c[mi][ni], ah[mi], bl0, bl1);
                }
            }
        }
    }

    #pragma unroll
    for (int mi = 0; mi < 2; mi++) {
        #pragma unroll
        for (int hf = 0; hf < 2; hf++) {
            const int r = wm * 32 + mi * 16 + hf * 8 + g;
            #pragma unroll
            for (int ni = 0; ni < 8; ni++) {
                const int j = j0 + wn * 64 + ni * 8 + t * 2;
                if (j < V) {
                    float2 o2;
                    o2.x = c[mi][ni][hf * 2 + 0] + b2[j];
                    o2.y = c[mi][ni][hf * 2 + 1] + b2[j + 1];
                    *(float2*)(g_logits + (size_t)r * V + j) = o2;
                }
            }
        }
    }
}

// ---------------------------------------------------------------------------
// K5a1: per-chunk max/sumexp (25 chunks of 2000 per row). grid=(B*25), 256thr.
// ---------------------------------------------------------------------------
__global__ void k5a1_part()
{
    const int blk = blockIdx.x;
    const int b = blk / 25, ch = blk - b * 25;
    const int t = threadIdx.x;
    const float* lr = g_logits + (size_t)b * V + ch * 2000;
    __shared__ float red[256];

    float mx = -1e30f;
    for (int j = t; j < 2000; j += 256) mx = fmaxf(mx, lr[j]);
    red[t] = mx;
    __syncthreads();
    for (int off = 128; off > 0; off >>= 1) {
        if (t < off) red[t] = fmaxf(red[t], red[t + off]);
        __syncthreads();
    }
    mx = red[0];
    __syncthreads();

    float s = 0.f;
    for (int j = t; j < 2000; j += 256) s += expf(lr[j] - mx);
    red[t] = s;
    __syncthreads();
    for (int off = 128; off > 0; off >>= 1) {
        if (t < off) red[t] += red[t + off];
        __syncthreads();
    }
    if (t == 0) { g_pmax[blk] = mx; g_psum[blk] = red[0]; }
}

// K5a2: combine. grid=(B), 32thr.
__global__ void k5a2_comb()
{
    const int b = blockIdx.x, lane = threadIdx.x;
    float pm = (lane < 25) ? g_pmax[b * 25 + lane] : -1e30f;
    float mx = pm;
    #pragma unroll
    for (int o = 16; o > 0; o >>= 1) mx = fmaxf(mx, __shfl_xor_sync(0xffffffffu, mx, o));
    float v = (lane < 25) ? g_psum[b * 25 + lane] * expf(pm - mx) : 0.f;
    v = wred(v);
    if (lane == 0) { g_rowmax[b] = mx; g_rowinv[b] = 1.f / v; }
}

// ---------------------------------------------------------------------------
__global__ void k5b_final(float* __restrict__ out)
{
    const int i = blockIdx.x * 256 + threadIdx.x;
    if (i >= B * VO) return;
    const int b = i / VO;
    const int c = i - b * VO;
    float v = 0.f;
    if (c < V) {
        const float gp = out[OFF_GP + b];
        v = expf(g_logits[(size_t)b * V + c] - g_rowmax[b]) * g_rowinv[b] * gp;
    }
    out[i] = v;
}

__global__ void k5c_scatter(const int* __restrict__ ewo, float* __restrict__ out)
{
    const int i = blockIdx.x * 256 + threadIdx.x;
    if (i >= B * S) return;
    const int b = i / S;
    const float gp = out[OFF_GP + b];
    const float a = out[OFF_AT + i];
    atomicAdd(out + (size_t)b * VO + ewo[i], a * (1.f - gp));
}

// ---------------------------------------------------------------------------
extern "C" void kernel_launch(void* const* d_in, const int* in_sizes, int n_in,
                              void* d_out, int out_size)
{
    const int*   idx      = (const int*)  d_in[0];
    const float* h0       = (const float*)d_in[1];
    const float* c0       = (const float*)d_in[2];
    const float* EO       = (const float*)d_in[3];
    const int*   emask    = (const int*)  d_in[4];
    const float* ctxv     = (const float*)d_in[5];
    const int*   ewo      = (const int*)  d_in[7];
    const float* coverage = (const float*)d_in[8];
    const float* emb      = (const float*)d_in[9];
    const float* Wi       = (const float*)d_in[10];
    const float* bi       = (const float*)d_in[11];
    const float* W_ih     = (const float*)d_in[12];
    const float* W_hh     = (const float*)d_in[13];
    const float* b_ih     = (const float*)d_in[14];
    const float* b_hh     = (const float*)d_in[15];
    const float* att_wh   = (const float*)d_in[16];
    const float* att_ws   = (const float*)d_in[17];
    const float* att_wc   = (const float*)d_in[18];
    const float* att_bc   = (const float*)d_in[19];
    const float* att_v    = (const float*)d_in[20];
    const float* gp_wh    = (const float*)d_in[21];
    const float* gp_bh    = (const float*)d_in[22];
    const float* gp_ws    = (const float*)d_in[23];
    const float* gp_bs    = (const float*)d_in[24];
    const float* gp_wx    = (const float*)d_in[25];
    const float* gp_bx    = (const float*)d_in[26];
    const float* out_w1   = (const float*)d_in[27];
    const float* out_b1   = (const float*)d_in[28];
    const float* out_w2   = (const float*)d_in[29];
    const float* out_b2   = (const float*)d_in[30];
    float* out = (float*)d_out;

    static int attr_done = 0;
    if (!attr_done) {
        cudaFuncSetAttribute(k2_mma, cudaFuncAttributeMaxDynamicSharedMemorySize, K2_SMEM);
        cudaFuncSetAttribute(k4_mma, cudaFuncAttributeMaxDynamicSharedMemorySize, K4_SMEM);
        attr_done = 1;
    }

    k0_wh<<<512, 256>>>(att_wh);
    k1_lstm<<<B, 256>>>(idx, h0, c0, ctxv, emb, Wi, bi, W_ih, W_hh, b_ih, b_hh,
                        att_ws, att_bc, gp_ws, gp_bs, gp_wx, gp_bx, gp_bh, out);
    k2_mma<<<(B * S) / 64, 512, K2_SMEM>>>(EO, att_wc, att_v, coverage, emask);
    k3_softmax_ctx<<<B, 512>>>(EO, coverage, gp_wh, out);
    {
        dim3 g3b(4, 2);
        k3b_hidden<<<g3b, 256>>>(out_w1, out_b1, out);
    }
    k4_mma<<<(V + 255) / 256, 512, K4_SMEM>>>(out_w2, out_b2);
    k5a1_part<<<B * 25, 256>>>();
    k5a2_comb<<<B, 32>>>();
    k5b_final<<<(B * VO + 255) / 256, 256>>>(out);
    k5c_scatter<<<(B * S + 255) / 256, 256>>>(ewo, out);
}

// round 6
// speedup vs baseline: 2.0204x; 1.1664x over previous
#include <cuda_runtime.h>
#include <cuda_fp16.h>
#include <math.h>

#define B 128
#define S 400
#define H 256
#define E 128
#define V 50000
#define OOV 50
#define TWOH 512
#define VO (V + OOV)

#define OFF_HT   (B * VO)
#define OFF_CT   (OFF_HT + B * H)
#define OFF_CTX  (OFF_CT + B * H)
#define OFF_AT   (OFF_CTX + B * TWOH)
#define OFF_GP   (OFF_AT + B * S)
#define OFF_COV  (OFF_GP + B)

__device__ float g_decbase[B * TWOH];
__device__ float g_gpart[B];
__device__ float g_et[B * S];
__device__ float g_hidden[B * H];
__device__ float g_logits[(size_t)B * V];
__device__ float g_rowmax[B];
__device__ float g_rowinv[B];
__device__ float g_pmax[B * 25];
__device__ float g_psum[B * 25];
__device__ float g_ctxpart[B * 4 * TWOH];
// Wh pre-split into fp16 hi/lo, k-pair packed, chunked: [16 chunks][512 n][16 kp]
__device__ unsigned g_WhHi[16 * 512 * 16];
__device__ unsigned g_WhLo[16 * 512 * 16];

__device__ __forceinline__ float sigf(float x) { return 1.0f / (1.0f + expf(-x)); }

__device__ __forceinline__ float wred(float a) {
    a += __shfl_xor_sync(0xffffffffu, a, 16);
    a += __shfl_xor_sync(0xffffffffu, a, 8);
    a += __shfl_xor_sync(0xffffffffu, a, 4);
    a += __shfl_xor_sync(0xffffffffu, a, 2);
    a += __shfl_xor_sync(0xffffffffu, a, 1);
    return a;
}

__device__ __forceinline__ void splitpack(float x, float y, unsigned& hi, unsigned& lo) {
    __half hx = __float2half_rn(x), hy = __float2half_rn(y);
    __half lx = __float2half_rn(x - __half2float(hx));
    __half ly = __float2half_rn(y - __half2float(hy));
    hi = ((unsigned)__half_as_ushort(hy) << 16) | (unsigned)__half_as_ushort(hx);
    lo = ((unsigned)__half_as_ushort(ly) << 16) | (unsigned)__half_as_ushort(lx);
}

__device__ __forceinline__ void mma16(float c[4], const unsigned a[4], unsigned b0, unsigned b1) {
    asm("mma.sync.aligned.m16n8k16.row.col.f32.f16.f16.f32 "
        "{%0,%1,%2,%3}, {%4,%5,%6,%7}, {%8,%9}, {%0,%1,%2,%3};"
        : "+f"(c[0]), "+f"(c[1]), "+f"(c[2]), "+f"(c[3])
        : "r"(a[0]), "r"(a[1]), "r"(a[2]), "r"(a[3]), "r"(b0), "r"(b1));
}

// ---------------------------------------------------------------------------
// K0: pre-split Wh into fp16 hi (and lo, unused by K2 now but cheap). grid=(512),256.
// ---------------------------------------------------------------------------
__global__ void k0_wh(const float* __restrict__ Wh)
{
    int idx = blockIdx.x * 256 + threadIdx.x;
    int n = idx >> 8;
    int kpg = idx & 255;
    int k = kpg * 2;
    int c = k >> 5, kp = (k & 31) >> 1;
    float2 v = *(const float2*)(Wh + (size_t)n * TWOH + k);
    unsigned hi, lo;
    splitpack(v.x, v.y, hi, lo);
    int d = (c * 512 + n) * 16 + kp;
    g_WhHi[d] = hi;
    g_WhLo[d] = lo;
}

// ---------------------------------------------------------------------------
// K1: embedding + input proj + LSTM + decbase + gen_p partial. grid=(B), 256thr.
// ---------------------------------------------------------------------------
__global__ void k1_lstm(
    const int* __restrict__ idx, const float* __restrict__ h0, const float* __restrict__ c0,
    const float* __restrict__ ctxv, const float* __restrict__ emb,
    const float* __restrict__ Wi, const float* __restrict__ bi,
    const float* __restrict__ W_ih, const float* __restrict__ W_hh,
    const float* __restrict__ b_ih, const float* __restrict__ b_hh,
    const float* __restrict__ att_ws, const float* __restrict__ att_bc,
    const float* __restrict__ gp_ws, const float* __restrict__ gp_bs,
    const float* __restrict__ gp_wx, const float* __restrict__ gp_bx,
    const float* __restrict__ gp_bh,
    float* __restrict__ out)
{
    const int b = blockIdx.x;
    const int tid = threadIdx.x;
    const int w = tid >> 5, lane = tid & 31;

    __shared__ float s_in[TWOH + E];
    __shared__ float s_x[E];
    __shared__ float s_h0[H];
    __shared__ float s_gates[4 * H];
    __shared__ float s_st[TWOH];
    __shared__ float s_red[256];

    for (int k = tid; k < TWOH; k += 256) s_in[k] = ctxv[b * TWOH + k];
    if (tid < E) s_in[TWOH + tid] = emb[(size_t)idx[b] * E + tid];
    s_h0[tid] = h0[b * H + tid];
    __syncthreads();

    for (int o = w * 16; o < (w + 1) * 16; o++) {
        const float* wr = Wi + (size_t)o * (TWOH + E);
        float a = 0.f;
        for (int k = lane; k < TWOH + E; k += 32) a += wr[k] * s_in[k];
        a = wred(a);
        if (lane == 0) s_x[o] = a + bi[o];
    }
    __syncthreads();

    for (int o = w * 128; o < (w + 1) * 128; o++) {
        const float* wi_ = W_ih + (size_t)o * E;
        const float* wh_ = W_hh + (size_t)o * H;
        float a = 0.f;
        for (int k = lane; k < E; k += 32) a += wi_[k] * s_x[k];
        for (int k = lane; k < H; k += 32) a += wh_[k] * s_h0[k];
        a = wred(a);
        if (lane == 0) s_gates[o] = a + b_ih[o] + b_hh[o];
    }
    __syncthreads();

    {
        float ig = sigf(s_gates[tid]);
        float fg = sigf(s_gates[H + tid]);
        float gg = tanhf(s_gates[2 * H + tid]);
        float og = sigf(s_gates[3 * H + tid]);
        float c = fg * c0[b * H + tid] + ig * gg;
        float h = og * tanhf(c);
        out[OFF_HT + b * H + tid] = h;
        out[OFF_CT + b * H + tid] = c;
        s_st[tid] = h;
        s_st[H + tid] = c;
    }
    __syncthreads();

    for (int o = w * 64; o < (w + 1) * 64; o++) {
        const float* wr = att_ws + (size_t)o * TWOH;
        float a = 0.f;
        for (int k = lane; k < TWOH; k += 32) a += wr[k] * s_st[k];
        a = wred(a);
        if (lane == 0) g_decbase[b * TWOH + o] = a + att_bc[o];
    }

    float p = 0.f;
    for (int k = tid; k < TWOH; k += 256) p += gp_ws[k] * s_st[k];
    if (tid < E) p += gp_wx[tid] * s_x[tid];
    s_red[tid] = p;
    __syncthreads();
    for (int off = 128; off > 0; off >>= 1) {
        if (tid < off) s_red[tid] += s_red[tid + off];
        __syncthreads();
    }
    if (tid == 0) g_gpart[b] = s_red[0] + gp_bs[0] + gp_bx[0] + gp_bh[0];
}

// ---------------------------------------------------------------------------
// K2: attention scores via fp16 mma m16n8k16, TWO products (ah*bh + al*bh).
// A (EO) is exactly hi/lo split; B (Wh) is single-rounded fp16 (hi only).
// Block: 64 rows x 512 n, K=512 in 16 chunks of 32. 512thr = 16 warps (2m x 8n).
// ---------------------------------------------------------------------------
#define K2P 20
#define K2_AH 0
#define K2_AL 5120
#define K2_BH 10240
#define K2_SV 51200
#define K2_SWC 53248
#define K2_SDB 55296
#define K2_EP 59392
#define K2_SMEM 61440

__global__ void __launch_bounds__(512, 1) k2_mma(
    const float* __restrict__ EO,
    const float* __restrict__ att_wc, const float* __restrict__ att_v,
    const float* __restrict__ coverage, const int* __restrict__ mask)
{
    extern __shared__ char smem[];
    unsigned* AHp = (unsigned*)(smem + K2_AH);
    unsigned* ALp = (unsigned*)(smem + K2_AL);
    unsigned* BHp = (unsigned*)(smem + K2_BH);
    float* sv  = (float*)(smem + K2_SV);
    float* swc = (float*)(smem + K2_SWC);
    float* sdb = (float*)(smem + K2_SDB);
    float* ep  = (float*)(smem + K2_EP);

    const int tid = threadIdx.x;
    const int w = tid >> 5, lane = tid & 31;
    const int g = lane >> 2, t = lane & 3;
    const int wm = w & 1, wn = w >> 1;
    const int row0 = blockIdx.x * 64;
    const int b0 = row0 / S;
    const int b1e = (row0 + 63) / S;

    if (tid < 512) {
        sv[tid] = att_v[tid];
        swc[tid] = att_wc[tid];
        sdb[tid] = g_decbase[b0 * TWOH + tid];
        sdb[512 + tid] = g_decbase[b1e * TWOH + tid];
    }

    float c[2][8][4];
    #pragma unroll
    for (int mi = 0; mi < 2; mi++)
        #pragma unroll
        for (int ni = 0; ni < 8; ni++)
            #pragma unroll
            for (int q = 0; q < 4; q++) c[mi][ni][q] = 0.f;

    for (int kt = 0; kt < 16; kt++) {
        const int k0 = kt * 32;
        __syncthreads();
        // A tile: 64 rows x 32 k -> hi/lo packed pairs
        {
            int r = tid >> 3, q = tid & 7;
            float4 v = *(const float4*)(EO + (size_t)(row0 + r) * TWOH + k0 + q * 4);
            unsigned h0_, l0_, h1_, l1_;
            splitpack(v.x, v.y, h0_, l0_);
            splitpack(v.z, v.w, h1_, l1_);
            *(uint2*)(AHp + r * K2P + q * 2) = make_uint2(h0_, h1_);
            *(uint2*)(ALp + r * K2P + q * 2) = make_uint2(l0_, l1_);
        }
        // B tile: 512 rows x 32 k, hi only
        #pragma unroll
        for (int i = 0; i < 4; i++) {
            int f = i * 512 + tid;
            int n = f >> 2, kq = f & 3;
            const uint4* srcH = (const uint4*)(g_WhHi + ((kt * 512 + n) * 16 + kq * 4));
            *(uint4*)(BHp + n * K2P + kq * 4) = *srcH;
        }
        __syncthreads();

        #pragma unroll
        for (int s = 0; s < 2; s++) {
            unsigned ah[2][4], al[2][4];
            #pragma unroll
            for (int mi = 0; mi < 2; mi++) {
                const unsigned* pa = AHp + (wm * 32 + mi * 16 + g) * K2P + s * 8 + t;
                ah[mi][0] = pa[0]; ah[mi][1] = pa[8 * K2P];
                ah[mi][2] = pa[4]; ah[mi][3] = pa[8 * K2P + 4];
                const unsigned* pl = ALp + (wm * 32 + mi * 16 + g) * K2P + s * 8 + t;
                al[mi][0] = pl[0]; al[mi][1] = pl[8 * K2P];
                al[mi][2] = pl[4]; al[mi][3] = pl[8 * K2P + 4];
            }
            #pragma unroll
            for (int ni = 0; ni < 8; ni++) {
                const unsigned* pb = BHp + (wn * 64 + ni * 8 + g) * K2P + s * 8 + t;
                unsigned bh0 = pb[0], bh1 = pb[4];
                #pragma unroll
                for (int mi = 0; mi < 2; mi++) {
                    mma16(c[mi][ni], ah[mi], bh0, bh1);
                    mma16(c[mi][ni], al[mi], bh0, bh1);
                }
            }
        }
    }

    // epilogue: exact tanh + v-dot; reduce over tg, then over 8 n-warps
    #pragma unroll
    for (int mi = 0; mi < 2; mi++) {
        #pragma unroll
        for (int hf = 0; hf < 2; hf++) {
            const int rl = wm * 32 + mi * 16 + hf * 8 + g;
            const int r = row0 + rl;
            const int dbo = (r / S != b0) ? 512 : 0;
            const float cov = coverage[r];
            float acc = 0.f;
            #pragma unroll
            for (int ni = 0; ni < 8; ni++) {
                const int j = wn * 64 + ni * 8 + t * 2;
                float v0 = c[mi][ni][hf * 2 + 0] + sdb[dbo + j] + cov * swc[j];
                float v1 = c[mi][ni][hf * 2 + 1] + sdb[dbo + j + 1] + cov * swc[j + 1];
                acc += sv[j] * tanhf(v0) + sv[j + 1] * tanhf(v1);
            }
            acc += __shfl_xor_sync(0xffffffffu, acc, 1);
            acc += __shfl_xor_sync(0xffffffffu, acc, 2);
            if (t == 0) ep[rl * 8 + wn] = acc;
        }
    }
    __syncthreads();
    if (tid < 64) {
        float sacc = 0.f;
        #pragma unroll
        for (int q = 0; q < 8; q++) sacc += ep[tid * 8 + q];
        const int r = row0 + tid;
        g_et[r] = (mask[r] == 0) ? -1e30f : sacc;
    }
}

// ---------------------------------------------------------------------------
// K3a: masked softmax over S -> a_t, next_coverage. grid=(B), 512thr.
// ---------------------------------------------------------------------------
__global__ void k3a_softmax(const float* __restrict__ coverage, float* __restrict__ out)
{
    const int b = blockIdx.x;
    const int t = threadIdx.x;
    __shared__ float red[512];

    float e = (t < S) ? g_et[b * S + t] : -1e30f;
    red[t] = e;
    __syncthreads();
    for (int off = 256; off > 0; off >>= 1) {
        if (t < off) red[t] = fmaxf(red[t], red[t + off]);
        __syncthreads();
    }
    const float mx = red[0];
    __syncthreads();

    float ex = (t < S) ? expf(e - mx) : 0.f;
    red[t] = ex;
    __syncthreads();
    for (int off = 256; off > 0; off >>= 1) {
        if (t < off) red[t] += red[t + off];
        __syncthreads();
    }
    const float inv = 1.f / red[0];

    if (t < S) {
        float a = ex * inv;
        out[OFF_AT + b * S + t] = a;
        out[OFF_COV + b * S + t] = coverage[b * S + t] + a;
    }
}

// ---------------------------------------------------------------------------
// K3c: ctx partials. grid=(B*4), 512thr. Block q of b handles s in [q*100,q*100+100).
// ---------------------------------------------------------------------------
__global__ void k3c_ctxpart(const float* __restrict__ EO, const float* __restrict__ out)
{
    const int blk = blockIdx.x;
    const int b = blk >> 2, q = blk & 3;
    const int t = threadIdx.x;
    __shared__ float sa[100];
    if (t < 100) sa[t] = out[OFF_AT + b * S + q * 100 + t];
    __syncthreads();
    const float* eob = EO + ((size_t)b * S + q * 100) * TWOH;
    float c = 0.f;
    #pragma unroll 10
    for (int s = 0; s < 100; s++) c += sa[s] * eob[(size_t)s * TWOH + t];
    g_ctxpart[(size_t)blk * TWOH + t] = c;
}

// ---------------------------------------------------------------------------
// K3d: combine ctx partials + gen_p. grid=(B), 512thr.
// ---------------------------------------------------------------------------
__global__ void k3d_ctx(const float* __restrict__ gp_wh, float* __restrict__ out)
{
    const int b = blockIdx.x;
    const int t = threadIdx.x;
    __shared__ float red[512];
    float c = g_ctxpart[(size_t)(b * 4 + 0) * TWOH + t]
            + g_ctxpart[(size_t)(b * 4 + 1) * TWOH + t]
            + g_ctxpart[(size_t)(b * 4 + 2) * TWOH + t]
            + g_ctxpart[(size_t)(b * 4 + 3) * TWOH + t];
    out[OFF_CTX + b * TWOH + t] = c;
    red[t] = gp_wh[t] * c;
    __syncthreads();
    for (int off = 256; off > 0; off >>= 1) {
        if (t < off) red[t] += red[t + off];
        __syncthreads();
    }
    if (t == 0) out[OFF_GP + b] = sigf(red[0] + g_gpart[b]);
}

// ---------------------------------------------------------------------------
// K3b: hidden = relu(out_w1 @ [h_t, ctx] + b1), tiled 64x64. grid=(4,2), 256thr.
// ---------------------------------------------------------------------------
__global__ void k3b_hidden(
    const float* __restrict__ out_w1, const float* __restrict__ out_b1,
    const float* __restrict__ out)
{
    __shared__ __align__(16) float As[16][68];
    __shared__ __align__(16) float Ws[16][68];

    const int tid = threadIdx.x;
    const int tx = tid & 15, ty = tid >> 4;
    const int rl = tid >> 2, kq = tid & 3;
    const int m0 = blockIdx.y * 64;
    const int n0 = blockIdx.x * 64;

    float acc[4][4];
    #pragma unroll
    for (int a = 0; a < 4; a++)
        #pragma unroll
        for (int c = 0; c < 4; c++) acc[a][c] = 0.f;

    for (int kt = 0; kt < 48; kt++) {
        const int k = kt * 16 + kq * 4;
        const int m = m0 + rl;
        float4 av = (k < H)
            ? *(const float4*)(out + OFF_HT + m * H + k)
            : *(const float4*)(out + OFF_CTX + m * TWOH + (k - H));
        float4 wv = *(const float4*)(out_w1 + (size_t)(n0 + rl) * (H + TWOH) + k);
        __syncthreads();
        As[kq * 4 + 0][rl] = av.x; As[kq * 4 + 1][rl] = av.y;
        As[kq * 4 + 2][rl] = av.z; As[kq * 4 + 3][rl] = av.w;
        Ws[kq * 4 + 0][rl] = wv.x; Ws[kq * 4 + 1][rl] = wv.y;
        Ws[kq * 4 + 2][rl] = wv.z; Ws[kq * 4 + 3][rl] = wv.w;
        __syncthreads();
        #pragma unroll
        for (int kk = 0; kk < 16; kk++) {
            float ar[4], wr[4];
            *(float4*)ar = *(const float4*)&As[kk][ty * 4];
            *(float4*)wr = *(const float4*)&Ws[kk][tx * 4];
            #pragma unroll
            for (int mi = 0; mi < 4; mi++)
                #pragma unroll
                for (int jj = 0; jj < 4; jj++)
                    acc[mi][jj] += ar[mi] * wr[jj];
        }
    }

    #pragma unroll
    for (int mi = 0; mi < 4; mi++) {
        const int m = m0 + ty * 4 + mi;
        #pragma unroll
        for (int jj = 0; jj < 4; jj++) {
            const int o = n0 + tx * 4 + jj;
            g_hidden[m * H + o] = fmaxf(acc[mi][jj] + out_b1[o], 0.f);
        }
    }
}

// ---------------------------------------------------------------------------
// K4: logits = hidden @ out_w2.T + b2, fp16 3-product mma (full accuracy).
// ---------------------------------------------------------------------------
#define K4_AH 0
#define K4_AL 10240
#define K4_BH 20480
#define K4_BL 40960
#define K4_SMEM 61440

__global__ void __launch_bounds__(512, 1) k4_mma(
    const float* __restrict__ W2, const float* __restrict__ b2)
{
    extern __shared__ char smem[];
    unsigned* AHp = (unsigned*)(smem + K4_AH);
    unsigned* ALp = (unsigned*)(smem + K4_AL);
    unsigned* BHp = (unsigned*)(smem + K4_BH);
    unsigned* BLp = (unsigned*)(smem + K4_BL);

    const int tid = threadIdx.x;
    const int w = tid >> 5, lane = tid & 31;
    const int g = lane >> 2, t = lane & 3;
    const int wm = w & 3, wn = w >> 2;
    const int j0 = blockIdx.x * 256;

    float c[2][8][4];
    #pragma unroll
    for (int mi = 0; mi < 2; mi++)
        #pragma unroll
        for (int ni = 0; ni < 8; ni++)
            #pragma unroll
            for (int q = 0; q < 4; q++) c[mi][ni][q] = 0.f;

    for (int kt = 0; kt < 8; kt++) {
        const int k0 = kt * 32;
        __syncthreads();
        #pragma unroll
        for (int i = 0; i < 2; i++) {
            int f = i * 512 + tid;
            int r = f >> 3, q = f & 7;
            float4 v = *(const float4*)(g_hidden + (size_t)r * H + k0 + q * 4);
            unsigned h0_, l0_, h1_, l1_;
            splitpack(v.x, v.y, h0_, l0_);
            splitpack(v.z, v.w, h1_, l1_);
            *(uint2*)(AHp + r * K2P + q * 2) = make_uint2(h0_, h1_);
            *(uint2*)(ALp + r * K2P + q * 2) = make_uint2(l0_, l1_);
        }
        #pragma unroll
        for (int i = 0; i < 4; i++) {
            int f = i * 512 + tid;
            int n = f >> 3, q = f & 7;
            int j = j0 + n;
            float4 v = make_float4(0.f, 0.f, 0.f, 0.f);
            if (j < V) v = *(const float4*)(W2 + (size_t)j * H + k0 + q * 4);
            unsigned h0_, l0_, h1_, l1_;
            splitpack(v.x, v.y, h0_, l0_);
            splitpack(v.z, v.w, h1_, l1_);
            *(uint2*)(BHp + n * K2P + q * 2) = make_uint2(h0_, h1_);
            *(uint2*)(BLp + n * K2P + q * 2) = make_uint2(l0_, l1_);
        }
        __syncthreads();

        #pragma unroll
        for (int s = 0; s < 2; s++) {
            unsigned ah[2][4], al[2][4];
            #pragma unroll
            for (int mi = 0; mi < 2; mi++) {
                const unsigned* pa = AHp + (wm * 32 + mi * 16 + g) * K2P + s * 8 + t;
                ah[mi][0] = pa[0]; ah[mi][1] = pa[8 * K2P];
                ah[mi][2] = pa[4]; ah[mi][3] = pa[8 * K2P + 4];
                const unsigned* pl = ALp + (wm * 32 + mi * 16 + g) * K2P + s * 8 + t;
                al[mi][0] = pl[0]; al[mi][1] = pl[8 * K2P];
                al[mi][2] = pl[4]; al[mi][3] = pl[8 * K2P + 4];
            }
            #pragma unroll
            for (int ni = 0; ni < 8; ni++) {
                const unsigned* pb = BHp + (wn * 64 + ni * 8 + g) * K2P + s * 8 + t;
                unsigned bh0 = pb[0], bh1 = pb[4];
                const unsigned* pbl = BLp + (wn * 64 + ni * 8 + g) * K2P + s * 8 + t;
                unsigned bl0 = pbl[0], bl1 = pbl[4];
                #pragma unroll
                for (int mi = 0; mi < 2; mi++) {
                    mma16(c[mi][ni], ah[mi], bh0, bh1);
                    mma16(c[mi][ni], al[mi], bh0, bh1);
                    mma16(c[mi][ni], ah[mi], bl0, bl1);
                }
            }
        }
    }

    #pragma unroll
    for (int mi = 0; mi < 2; mi++) {
        #pragma unroll
        for (int hf = 0; hf < 2; hf++) {
            const int r = wm * 32 + mi * 16 + hf * 8 + g;
            #pragma unroll
            for (int ni = 0; ni < 8; ni++) {
                const int j = j0 + wn * 64 + ni * 8 + t * 2;
                if (j < V) {
                    float2 o2;
                    o2.x = c[mi][ni][hf * 2 + 0] + b2[j];
                    o2.y = c[mi][ni][hf * 2 + 1] + b2[j + 1];
                    *(float2*)(g_logits + (size_t)r * V + j) = o2;
                }
            }
        }
    }
}

// ---------------------------------------------------------------------------
__global__ void k5a1_part()
{
    const int blk = blockIdx.x;
    const int b = blk / 25, ch = blk - b * 25;
    const int t = threadIdx.x;
    const float* lr = g_logits + (size_t)b * V + ch * 2000;
    __shared__ float red[256];

    float mx = -1e30f;
    for (int j = t; j < 2000; j += 256) mx = fmaxf(mx, lr[j]);
    red[t] = mx;
    __syncthreads();
    for (int off = 128; off > 0; off >>= 1) {
        if (t < off) red[t] = fmaxf(red[t], red[t + off]);
        __syncthreads();
    }
    mx = red[0];
    __syncthreads();

    float s = 0.f;
    for (int j = t; j < 2000; j += 256) s += expf(lr[j] - mx);
    red[t] = s;
    __syncthreads();
    for (int off = 128; off > 0; off >>= 1) {
        if (t < off) red[t] += red[t + off];
        __syncthreads();
    }
    if (t == 0) { g_pmax[blk] = mx; g_psum[blk] = red[0]; }
}

__global__ void k5a2_comb()
{
    const int b = blockIdx.x, lane = threadIdx.x;
    float pm = (lane < 25) ? g_pmax[b * 25 + lane] : -1e30f;
    float mx = pm;
    #pragma unroll
    for (int o = 16; o > 0; o >>= 1) mx = fmaxf(mx, __shfl_xor_sync(0xffffffffu, mx, o));
    float v = (lane < 25) ? g_psum[b * 25 + lane] * expf(pm - mx) : 0.f;
    v = wred(v);
    if (lane == 0) { g_rowmax[b] = mx; g_rowinv[b] = 1.f / v; }
}

__global__ void k5b_final(float* __restrict__ out)
{
    const int i = blockIdx.x * 256 + threadIdx.x;
    if (i >= B * VO) return;
    const int b = i / VO;
    const int c = i - b * VO;
    float v = 0.f;
    if (c < V) {
        const float gp = out[OFF_GP + b];
        v = expf(g_logits[(size_t)b * V + c] - g_rowmax[b]) * g_rowinv[b] * gp;
    }
    out[i] = v;
}

__global__ void k5c_scatter(const int* __restrict__ ewo, float* __restrict__ out)
{
    const int i = blockIdx.x * 256 + threadIdx.x;
    if (i >= B * S) return;
    const int b = i / S;
    const float gp = out[OFF_GP + b];
    const float a = out[OFF_AT + i];
    atomicAdd(out + (size_t)b * VO + ewo[i], a * (1.f - gp));
}

// ---------------------------------------------------------------------------
extern "C" void kernel_launch(void* const* d_in, const int* in_sizes, int n_in,
                              void* d_out, int out_size)
{
    const int*   idx      = (const int*)  d_in[0];
    const float* h0       = (const float*)d_in[1];
    const float* c0       = (const float*)d_in[2];
    const float* EO       = (const float*)d_in[3];
    const int*   emask    = (const int*)  d_in[4];
    const float* ctxv     = (const float*)d_in[5];
    const int*   ewo      = (const int*)  d_in[7];
    const float* coverage = (const float*)d_in[8];
    const float* emb      = (const float*)d_in[9];
    const float* Wi       = (const float*)d_in[10];
    const float* bi       = (const float*)d_in[11];
    const float* W_ih     = (const float*)d_in[12];
    const float* W_hh     = (const float*)d_in[13];
    const float* b_ih     = (const float*)d_in[14];
    const float* b_hh     = (const float*)d_in[15];
    const float* att_wh   = (const float*)d_in[16];
    const float* att_ws   = (const float*)d_in[17];
    const float* att_wc   = (const float*)d_in[18];
    const float* att_bc   = (const float*)d_in[19];
    const float* att_v    = (const float*)d_in[20];
    const float* gp_wh    = (const float*)d_in[21];
    const float* gp_bh    = (const float*)d_in[22];
    const float* gp_ws    = (const float*)d_in[23];
    const float* gp_bs    = (const float*)d_in[24];
    const float* gp_wx    = (const float*)d_in[25];
    const float* gp_bx    = (const float*)d_in[26];
    const float* out_w1   = (const float*)d_in[27];
    const float* out_b1   = (const float*)d_in[28];
    const float* out_w2   = (const float*)d_in[29];
    const float* out_b2   = (const float*)d_in[30];
    float* out = (float*)d_out;

    static int attr_done = 0;
    if (!attr_done) {
        cudaFuncSetAttribute(k2_mma, cudaFuncAttributeMaxDynamicSharedMemorySize, K2_SMEM);
        cudaFuncSetAttribute(k4_mma, cudaFuncAttributeMaxDynamicSharedMemorySize, K4_SMEM);
        attr_done = 1;
    }

    k0_wh<<<512, 256>>>(att_wh);
    k1_lstm<<<B, 256>>>(idx, h0, c0, ctxv, emb, Wi, bi, W_ih, W_hh, b_ih, b_hh,
                        att_ws, att_bc, gp_ws, gp_bs, gp_wx, gp_bx, gp_bh, out);
    k2_mma<<<(B * S) / 64, 512, K2_SMEM>>>(EO, att_wc, att_v, coverage, emask);
    k3a_softmax<<<B, 512>>>(coverage, out);
    k3c_ctxpart<<<B * 4, 512>>>(EO, out);
    k3d_ctx<<<B, 512>>>(gp_wh, out);
    {
        dim3 g3b(4, 2);
        k3b_hidden<<<g3b, 256>>>(out_w1, out_b1, out);
    }
    k4_mma<<<(V + 255) / 256, 512, K4_SMEM>>>(out_w2, out_b2);
    k5a1_part<<<B * 25, 256>>>();
    k5a2_comb<<<B, 32>>>();
    k5b_final<<<(B * VO + 255) / 256, 256>>>(out);
    k5c_scatter<<<(B * S + 255) / 256, 256>>>(ewo, out);
}

// round 7
// speedup vs baseline: 2.1090x; 1.0439x over previous
#include <cuda_runtime.h>
#include <cuda_fp16.h>
#include <math.h>

#define B 128
#define S 400
#define H 256
#define E 128
#define V 50000
#define OOV 50
#define TWOH 512
#define VO (V + OOV)

#define OFF_HT   (B * VO)
#define OFF_CT   (OFF_HT + B * H)
#define OFF_CTX  (OFF_CT + B * H)
#define OFF_AT   (OFF_CTX + B * TWOH)
#define OFF_GP   (OFF_AT + B * S)
#define OFF_COV  (OFF_GP + B)

__device__ float g_decbase[B * TWOH];
__device__ float g_gpart[B];
__device__ float g_et[B * S];
__device__ float g_hidden[B * H];
__device__ float g_logits[(size_t)B * V];
__device__ float g_rowmax[B];
__device__ float g_rowinv[B];
__device__ float g_pmax[B * 25];
__device__ float g_psum[B * 25];
__device__ float g_ctxpart[B * 4 * TWOH];
// Wh pre-split fp16 hi, k-pair packed, chunked: [16 chunks][512 n][16 kp]
__device__ unsigned g_WhHi[16 * 512 * 16];

__device__ __forceinline__ float sigf(float x) { return 1.0f / (1.0f + expf(-x)); }

__device__ __forceinline__ float wred(float a) {
    a += __shfl_xor_sync(0xffffffffu, a, 16);
    a += __shfl_xor_sync(0xffffffffu, a, 8);
    a += __shfl_xor_sync(0xffffffffu, a, 4);
    a += __shfl_xor_sync(0xffffffffu, a, 2);
    a += __shfl_xor_sync(0xffffffffu, a, 1);
    return a;
}

__device__ __forceinline__ void splitpack(float x, float y, unsigned& hi, unsigned& lo) {
    __half hx = __float2half_rn(x), hy = __float2half_rn(y);
    __half lx = __float2half_rn(x - __half2float(hx));
    __half ly = __float2half_rn(y - __half2float(hy));
    hi = ((unsigned)__half_as_ushort(hy) << 16) | (unsigned)__half_as_ushort(hx);
    lo = ((unsigned)__half_as_ushort(ly) << 16) | (unsigned)__half_as_ushort(lx);
}

__device__ __forceinline__ void mma16(float c[4], const unsigned a[4], unsigned b0, unsigned b1) {
    asm("mma.sync.aligned.m16n8k16.row.col.f32.f16.f16.f32 "
        "{%0,%1,%2,%3}, {%4,%5,%6,%7}, {%8,%9}, {%0,%1,%2,%3};"
        : "+f"(c[0]), "+f"(c[1]), "+f"(c[2]), "+f"(c[3])
        : "r"(a[0]), "r"(a[1]), "r"(a[2]), "r"(a[3]), "r"(b0), "r"(b1));
}

// ---------------------------------------------------------------------------
// K0: pre-split Wh into fp16 hi, k-pair packed. grid=(512), 256thr.
// ---------------------------------------------------------------------------
__global__ void k0_wh(const float* __restrict__ Wh)
{
    int idx = blockIdx.x * 256 + threadIdx.x;
    int n = idx >> 8;
    int kpg = idx & 255;
    int k = kpg * 2;
    int c = k >> 5, kp = (k & 31) >> 1;
    float2 v = *(const float2*)(Wh + (size_t)n * TWOH + k);
    unsigned hi, lo;
    splitpack(v.x, v.y, hi, lo);
    g_WhHi[(c * 512 + n) * 16 + kp] = hi;
}

// ---------------------------------------------------------------------------
// K1: embedding + input proj + LSTM + decbase + gen_p partial. grid=(B), 256thr.
// ---------------------------------------------------------------------------
__global__ void k1_lstm(
    const int* __restrict__ idx, const float* __restrict__ h0, const float* __restrict__ c0,
    const float* __restrict__ ctxv, const float* __restrict__ emb,
    const float* __restrict__ Wi, const float* __restrict__ bi,
    const float* __restrict__ W_ih, const float* __restrict__ W_hh,
    const float* __restrict__ b_ih, const float* __restrict__ b_hh,
    const float* __restrict__ att_ws, const float* __restrict__ att_bc,
    const float* __restrict__ gp_ws, const float* __restrict__ gp_bs,
    const float* __restrict__ gp_wx, const float* __restrict__ gp_bx,
    const float* __restrict__ gp_bh,
    float* __restrict__ out)
{
    const int b = blockIdx.x;
    const int tid = threadIdx.x;
    const int w = tid >> 5, lane = tid & 31;

    __shared__ float s_in[TWOH + E];
    __shared__ float s_x[E];
    __shared__ float s_h0[H];
    __shared__ float s_gates[4 * H];
    __shared__ float s_st[TWOH];
    __shared__ float s_red[256];

    for (int k = tid; k < TWOH; k += 256) s_in[k] = ctxv[b * TWOH + k];
    if (tid < E) s_in[TWOH + tid] = emb[(size_t)idx[b] * E + tid];
    s_h0[tid] = h0[b * H + tid];
    __syncthreads();

    for (int o = w * 16; o < (w + 1) * 16; o++) {
        const float* wr = Wi + (size_t)o * (TWOH + E);
        float a = 0.f;
        for (int k = lane; k < TWOH + E; k += 32) a += wr[k] * s_in[k];
        a = wred(a);
        if (lane == 0) s_x[o] = a + bi[o];
    }
    __syncthreads();

    for (int o = w * 128; o < (w + 1) * 128; o++) {
        const float* wi_ = W_ih + (size_t)o * E;
        const float* wh_ = W_hh + (size_t)o * H;
        float a = 0.f;
        for (int k = lane; k < E; k += 32) a += wi_[k] * s_x[k];
        for (int k = lane; k < H; k += 32) a += wh_[k] * s_h0[k];
        a = wred(a);
        if (lane == 0) s_gates[o] = a + b_ih[o] + b_hh[o];
    }
    __syncthreads();

    {
        float ig = sigf(s_gates[tid]);
        float fg = sigf(s_gates[H + tid]);
        float gg = tanhf(s_gates[2 * H + tid]);
        float og = sigf(s_gates[3 * H + tid]);
        float c = fg * c0[b * H + tid] + ig * gg;
        float h = og * tanhf(c);
        out[OFF_HT + b * H + tid] = h;
        out[OFF_CT + b * H + tid] = c;
        s_st[tid] = h;
        s_st[H + tid] = c;
    }
    __syncthreads();

    for (int o = w * 64; o < (w + 1) * 64; o++) {
        const float* wr = att_ws + (size_t)o * TWOH;
        float a = 0.f;
        for (int k = lane; k < TWOH; k += 32) a += wr[k] * s_st[k];
        a = wred(a);
        if (lane == 0) g_decbase[b * TWOH + o] = a + att_bc[o];
    }

    float p = 0.f;
    for (int k = tid; k < TWOH; k += 256) p += gp_ws[k] * s_st[k];
    if (tid < E) p += gp_wx[tid] * s_x[tid];
    s_red[tid] = p;
    __syncthreads();
    for (int off = 128; off > 0; off >>= 1) {
        if (tid < off) s_red[tid] += s_red[tid + off];
        __syncthreads();
    }
    if (tid == 0) g_gpart[b] = s_red[0] + gp_bs[0] + gp_bx[0] + gp_bh[0];
}

// ---------------------------------------------------------------------------
// K2: attention scores, fp16 mma two-product, double-buffered pipeline.
// Block: 64 rows x 512 n, K=512 in 16 chunks of 32. 512thr = 16 warps (2m x 8n).
// Per buffer: AH [64][20]u32 (5120B) | AL (5120B) | BH [512][20]u32 (40960B).
// ---------------------------------------------------------------------------
#define K2P 20
#define K2_BUF 51200
#define K2_AH 0
#define K2_AL 5120
#define K2_BH 10240
#define K2_SV  102400
#define K2_SWC 104448
#define K2_SDB 106496
#define K2_EP  110592
#define K2_SMEM 112640

__global__ void __launch_bounds__(512, 1) k2_mma(
    const float* __restrict__ EO,
    const float* __restrict__ att_wc, const float* __restrict__ att_v,
    const float* __restrict__ coverage, const int* __restrict__ mask)
{
    extern __shared__ char smem[];
    float* sv  = (float*)(smem + K2_SV);
    float* swc = (float*)(smem + K2_SWC);
    float* sdb = (float*)(smem + K2_SDB);
    float* ep  = (float*)(smem + K2_EP);

    const int tid = threadIdx.x;
    const int w = tid >> 5, lane = tid & 31;
    const int g = lane >> 2, t = lane & 3;
    const int wm = w & 1, wn = w >> 1;
    const int row0 = blockIdx.x * 64;
    const int b0 = row0 / S;
    const int b1e = (row0 + 63) / S;

    if (tid < 512) {
        sv[tid] = att_v[tid];
        swc[tid] = att_wc[tid];
        sdb[tid] = g_decbase[b0 * TWOH + tid];
        sdb[512 + tid] = g_decbase[b1e * TWOH + tid];
    }

    // staging indices
    const int ar = tid >> 3, aq = tid & 7;           // A: row, quad
    const int bn = tid >> 2, bkq = tid & 3;          // B: base n, quad (n_i = i*128+bn)
    const float* aptr = EO + (size_t)(row0 + ar) * TWOH + aq * 4;

    float c[2][8][4];
    #pragma unroll
    for (int mi = 0; mi < 2; mi++)
        #pragma unroll
        for (int ni = 0; ni < 8; ni++)
            #pragma unroll
            for (int q = 0; q < 4; q++) c[mi][ni][q] = 0.f;

    float4 av;
    uint4 bv[4];

    // prologue: chunk 0 loads
    av = *(const float4*)(aptr);
    #pragma unroll
    for (int i = 0; i < 4; i++)
        bv[i] = *(const uint4*)(g_WhHi + ((size_t)(0 * 512 + i * 128 + bn) * 16 + bkq * 4));
    {
        unsigned h0_, l0_, h1_, l1_;
        splitpack(av.x, av.y, h0_, l0_);
        splitpack(av.z, av.w, h1_, l1_);
        unsigned* AHp = (unsigned*)(smem + K2_AH);
        unsigned* ALp = (unsigned*)(smem + K2_AL);
        unsigned* BHp = (unsigned*)(smem + K2_BH);
        *(uint2*)(AHp + ar * K2P + aq * 2) = make_uint2(h0_, h1_);
        *(uint2*)(ALp + ar * K2P + aq * 2) = make_uint2(l0_, l1_);
        #pragma unroll
        for (int i = 0; i < 4; i++)
            *(uint4*)(BHp + (i * 128 + bn) * K2P + bkq * 4) = bv[i];
    }
    __syncthreads();

    for (int kt = 0; kt < 16; kt++) {
        char* bufc = smem + (kt & 1) * K2_BUF;
        // issue next-chunk loads early (latency hides under mma)
        if (kt < 15) {
            av = *(const float4*)(aptr + (kt + 1) * 32);
            #pragma unroll
            for (int i = 0; i < 4; i++)
                bv[i] = *(const uint4*)(g_WhHi + ((size_t)((kt + 1) * 512 + i * 128 + bn) * 16 + bkq * 4));
        }

        unsigned* AHc = (unsigned*)(bufc + K2_AH);
        unsigned* ALc = (unsigned*)(bufc + K2_AL);
        unsigned* BHc = (unsigned*)(bufc + K2_BH);
        #pragma unroll
        for (int s = 0; s < 2; s++) {
            unsigned ah[2][4], al[2][4];
            #pragma unroll
            for (int mi = 0; mi < 2; mi++) {
                const unsigned* pa = AHc + (wm * 32 + mi * 16 + g) * K2P + s * 8 + t;
                ah[mi][0] = pa[0]; ah[mi][1] = pa[8 * K2P];
                ah[mi][2] = pa[4]; ah[mi][3] = pa[8 * K2P + 4];
                const unsigned* pl = ALc + (wm * 32 + mi * 16 + g) * K2P + s * 8 + t;
                al[mi][0] = pl[0]; al[mi][1] = pl[8 * K2P];
                al[mi][2] = pl[4]; al[mi][3] = pl[8 * K2P + 4];
            }
            #pragma unroll
            for (int ni = 0; ni < 8; ni++) {
                const unsigned* pb = BHc + (wn * 64 + ni * 8 + g) * K2P + s * 8 + t;
                unsigned bh0 = pb[0], bh1 = pb[4];
                #pragma unroll
                for (int mi = 0; mi < 2; mi++) {
                    mma16(c[mi][ni], ah[mi], bh0, bh1);
                    mma16(c[mi][ni], al[mi], bh0, bh1);
                }
            }
        }

        if (kt < 15) {
            char* bufn = smem + ((kt + 1) & 1) * K2_BUF;
            unsigned h0_, l0_, h1_, l1_;
            splitpack(av.x, av.y, h0_, l0_);
            splitpack(av.z, av.w, h1_, l1_);
            *(uint2*)((unsigned*)(bufn + K2_AH) + ar * K2P + aq * 2) = make_uint2(h0_, h1_);
            *(uint2*)((unsigned*)(bufn + K2_AL) + ar * K2P + aq * 2) = make_uint2(l0_, l1_);
            unsigned* BHn = (unsigned*)(bufn + K2_BH);
            #pragma unroll
            for (int i = 0; i < 4; i++)
                *(uint4*)(BHn + (i * 128 + bn) * K2P + bkq * 4) = bv[i];
        }
        __syncthreads();
    }

    // epilogue: exact tanh + v-dot; reduce over tg, then over 8 n-warps
    #pragma unroll
    for (int mi = 0; mi < 2; mi++) {
        #pragma unroll
        for (int hf = 0; hf < 2; hf++) {
            const int rl = wm * 32 + mi * 16 + hf * 8 + g;
            const int r = row0 + rl;
            const int dbo = (r / S != b0) ? 512 : 0;
            const float cov = coverage[r];
            float acc = 0.f;
            #pragma unroll
            for (int ni = 0; ni < 8; ni++) {
                const int j = wn * 64 + ni * 8 + t * 2;
                float v0 = c[mi][ni][hf * 2 + 0] + sdb[dbo + j] + cov * swc[j];
                float v1 = c[mi][ni][hf * 2 + 1] + sdb[dbo + j + 1] + cov * swc[j + 1];
                acc += sv[j] * tanhf(v0) + sv[j + 1] * tanhf(v1);
            }
            acc += __shfl_xor_sync(0xffffffffu, acc, 1);
            acc += __shfl_xor_sync(0xffffffffu, acc, 2);
            if (t == 0) ep[rl * 8 + wn] = acc;
        }
    }
    __syncthreads();
    if (tid < 64) {
        float sacc = 0.f;
        #pragma unroll
        for (int q = 0; q < 8; q++) sacc += ep[tid * 8 + q];
        const int r = row0 + tid;
        g_et[r] = (mask[r] == 0) ? -1e30f : sacc;
    }
}

// ---------------------------------------------------------------------------
// K3a: masked softmax over S -> a_t, next_coverage. grid=(B), 512thr.
// ---------------------------------------------------------------------------
__global__ void k3a_softmax(const float* __restrict__ coverage, float* __restrict__ out)
{
    const int b = blockIdx.x;
    const int t = threadIdx.x;
    __shared__ float red[512];

    float e = (t < S) ? g_et[b * S + t] : -1e30f;
    red[t] = e;
    __syncthreads();
    for (int off = 256; off > 0; off >>= 1) {
        if (t < off) red[t] = fmaxf(red[t], red[t + off]);
        __syncthreads();
    }
    const float mx = red[0];
    __syncthreads();

    float ex = (t < S) ? expf(e - mx) : 0.f;
    red[t] = ex;
    __syncthreads();
    for (int off = 256; off > 0; off >>= 1) {
        if (t < off) red[t] += red[t + off];
        __syncthreads();
    }
    const float inv = 1.f / red[0];

    if (t < S) {
        float a = ex * inv;
        out[OFF_AT + b * S + t] = a;
        out[OFF_COV + b * S + t] = coverage[b * S + t] + a;
    }
}

// ---------------------------------------------------------------------------
// K3c: ctx partials. grid=(B*4), 512thr.
// ---------------------------------------------------------------------------
__global__ void k3c_ctxpart(const float* __restrict__ EO, const float* __restrict__ out)
{
    const int blk = blockIdx.x;
    const int b = blk >> 2, q = blk & 3;
    const int t = threadIdx.x;
    __shared__ float sa[100];
    if (t < 100) sa[t] = out[OFF_AT + b * S + q * 100 + t];
    __syncthreads();
    const float* eob = EO + ((size_t)b * S + q * 100) * TWOH;
    float c = 0.f;
    #pragma unroll 10
    for (int s = 0; s < 100; s++) c += sa[s] * eob[(size_t)s * TWOH + t];
    g_ctxpart[(size_t)blk * TWOH + t] = c;
}

// ---------------------------------------------------------------------------
// K3d: combine ctx partials + gen_p. grid=(B), 512thr.
// ---------------------------------------------------------------------------
__global__ void k3d_ctx(const float* __restrict__ gp_wh, float* __restrict__ out)
{
    const int b = blockIdx.x;
    const int t = threadIdx.x;
    __shared__ float red[512];
    float c = g_ctxpart[(size_t)(b * 4 + 0) * TWOH + t]
            + g_ctxpart[(size_t)(b * 4 + 1) * TWOH + t]
            + g_ctxpart[(size_t)(b * 4 + 2) * TWOH + t]
            + g_ctxpart[(size_t)(b * 4 + 3) * TWOH + t];
    out[OFF_CTX + b * TWOH + t] = c;
    red[t] = gp_wh[t] * c;
    __syncthreads();
    for (int off = 256; off > 0; off >>= 1) {
        if (t < off) red[t] += red[t + off];
        __syncthreads();
    }
    if (t == 0) out[OFF_GP + b] = sigf(red[0] + g_gpart[b]);
}

// ---------------------------------------------------------------------------
// K3b: hidden = relu(out_w1 @ [h_t, ctx] + b1), tiled 64x64. grid=(4,2), 256thr.
// ---------------------------------------------------------------------------
__global__ void k3b_hidden(
    const float* __restrict__ out_w1, const float* __restrict__ out_b1,
    const float* __restrict__ out)
{
    __shared__ __align__(16) float As[16][68];
    __shared__ __align__(16) float Ws[16][68];

    const int tid = threadIdx.x;
    const int tx = tid & 15, ty = tid >> 4;
    const int rl = tid >> 2, kq = tid & 3;
    const int m0 = blockIdx.y * 64;
    const int n0 = blockIdx.x * 64;

    float acc[4][4];
    #pragma unroll
    for (int a = 0; a < 4; a++)
        #pragma unroll
        for (int c = 0; c < 4; c++) acc[a][c] = 0.f;

    for (int kt = 0; kt < 48; kt++) {
        const int k = kt * 16 + kq * 4;
        const int m = m0 + rl;
        float4 av = (k < H)
            ? *(const float4*)(out + OFF_HT + m * H + k)
            : *(const float4*)(out + OFF_CTX + m * TWOH + (k - H));
        float4 wv = *(const float4*)(out_w1 + (size_t)(n0 + rl) * (H + TWOH) + k);
        __syncthreads();
        As[kq * 4 + 0][rl] = av.x; As[kq * 4 + 1][rl] = av.y;
        As[kq * 4 + 2][rl] = av.z; As[kq * 4 + 3][rl] = av.w;
        Ws[kq * 4 + 0][rl] = wv.x; Ws[kq * 4 + 1][rl] = wv.y;
        Ws[kq * 4 + 2][rl] = wv.z; Ws[kq * 4 + 3][rl] = wv.w;
        __syncthreads();
        #pragma unroll
        for (int kk = 0; kk < 16; kk++) {
            float ar[4], wr[4];
            *(float4*)ar = *(const float4*)&As[kk][ty * 4];
            *(float4*)wr = *(const float4*)&Ws[kk][tx * 4];
            #pragma unroll
            for (int mi = 0; mi < 4; mi++)
                #pragma unroll
                for (int jj = 0; jj < 4; jj++)
                    acc[mi][jj] += ar[mi] * wr[jj];
        }
    }

    #pragma unroll
    for (int mi = 0; mi < 4; mi++) {
        const int m = m0 + ty * 4 + mi;
        #pragma unroll
        for (int jj = 0; jj < 4; jj++) {
            const int o = n0 + tx * 4 + jj;
            g_hidden[m * H + o] = fmaxf(acc[mi][jj] + out_b1[o], 0.f);
        }
    }
}

// ---------------------------------------------------------------------------
// K4: logits = hidden @ out_w2.T + b2, fp16 two-product, double-buffered.
// Block 128m x 256n, K=256 (8 chunks of 32). 512thr = 16 warps (4m x 4n).
// Per buffer: AH [128][20] (10240B) | AL (10240B) | BH [256][20] (20480B).
// ---------------------------------------------------------------------------
#define K4_BUF 40960
#define K4_AH 0
#define K4_AL 10240
#define K4_BH 20480
#define K4_SMEM 81920

__global__ void __launch_bounds__(512, 1) k4_mma(
    const float* __restrict__ W2, const float* __restrict__ b2)
{
    extern __shared__ char smem[];

    const int tid = threadIdx.x;
    const int w = tid >> 5, lane = tid & 31;
    const int g = lane >> 2, t = lane & 3;
    const int wm = w & 3, wn = w >> 2;
    const int j0 = blockIdx.x * 256;

    const int ar = tid >> 3, aq = tid & 7;   // A: r_i = i*64+ar
    const int br = tid >> 3, bq = tid & 7;   // B: n_i = i*64+br

    float c[2][8][4];
    #pragma unroll
    for (int mi = 0; mi < 2; mi++)
        #pragma unroll
        for (int ni = 0; ni < 8; ni++)
            #pragma unroll
            for (int q = 0; q < 4; q++) c[mi][ni][q] = 0.f;

    float4 avv[2], bvv[4];

    // prologue chunk 0
    #pragma unroll
    for (int i = 0; i < 2; i++)
        avv[i] = *(const float4*)(g_hidden + (size_t)(i * 64 + ar) * H + aq * 4);
    #pragma unroll
    for (int i = 0; i < 4; i++) {
        int j = j0 + i * 64 + br;
        bvv[i] = (j < V) ? *(const float4*)(W2 + (size_t)j * H + bq * 4)
                         : make_float4(0.f, 0.f, 0.f, 0.f);
    }
    {
        unsigned* AHp = (unsigned*)(smem + K4_AH);
        unsigned* ALp = (unsigned*)(smem + K4_AL);
        unsigned* BHp = (unsigned*)(smem + K4_BH);
        #pragma unroll
        for (int i = 0; i < 2; i++) {
            unsigned h0_, l0_, h1_, l1_;
            splitpack(avv[i].x, avv[i].y, h0_, l0_);
            splitpack(avv[i].z, avv[i].w, h1_, l1_);
            *(uint2*)(AHp + (i * 64 + ar) * K2P + aq * 2) = make_uint2(h0_, h1_);
            *(uint2*)(ALp + (i * 64 + ar) * K2P + aq * 2) = make_uint2(l0_, l1_);
        }
        #pragma unroll
        for (int i = 0; i < 4; i++) {
            unsigned h0_, l0_, h1_, l1_;
            splitpack(bvv[i].x, bvv[i].y, h0_, l0_);
            splitpack(bvv[i].z, bvv[i].w, h1_, l1_);
            *(uint2*)(BHp + (i * 64 + br) * K2P + bq * 2) = make_uint2(h0_, h1_);
        }
    }
    __syncthreads();

    for (int kt = 0; kt < 8; kt++) {
        char* bufc = smem + (kt & 1) * K4_BUF;
        if (kt < 7) {
            const int k0 = (kt + 1) * 32;
            #pragma unroll
            for (int i = 0; i < 2; i++)
                avv[i] = *(const float4*)(g_hidden + (size_t)(i * 64 + ar) * H + k0 + aq * 4);
            #pragma unroll
            for (int i = 0; i < 4; i++) {
                int j = j0 + i * 64 + br;
                bvv[i] = (j < V) ? *(const float4*)(W2 + (size_t)j * H + k0 + bq * 4)
                                 : make_float4(0.f, 0.f, 0.f, 0.f);
            }
        }

        unsigned* AHc = (unsigned*)(bufc + K4_AH);
        unsigned* ALc = (unsigned*)(bufc + K4_AL);
        unsigned* BHc = (unsigned*)(bufc + K4_BH);
        #pragma unroll
        for (int s = 0; s < 2; s++) {
            unsigned ah[2][4], al[2][4];
            #pragma unroll
            for (int mi = 0; mi < 2; mi++) {
                const unsigned* pa = AHc + (wm * 32 + mi * 16 + g) * K2P + s * 8 + t;
                ah[mi][0] = pa[0]; ah[mi][1] = pa[8 * K2P];
                ah[mi][2] = pa[4]; ah[mi][3] = pa[8 * K2P + 4];
                const unsigned* pl = ALc + (wm * 32 + mi * 16 + g) * K2P + s * 8 + t;
                al[mi][0] = pl[0]; al[mi][1] = pl[8 * K2P];
                al[mi][2] = pl[4]; al[mi][3] = pl[8 * K2P + 4];
            }
            #pragma unroll
            for (int ni = 0; ni < 8; ni++) {
                const unsigned* pb = BHc + (wn * 64 + ni * 8 + g) * K2P + s * 8 + t;
                unsigned bh0 = pb[0], bh1 = pb[4];
                #pragma unroll
                for (int mi = 0; mi < 2; mi++) {
                    mma16(c[mi][ni], ah[mi], bh0, bh1);
                    mma16(c[mi][ni], al[mi], bh0, bh1);
                }
            }
        }

        if (kt < 7) {
            char* bufn = smem + ((kt + 1) & 1) * K4_BUF;
            unsigned* AHn = (unsigned*)(bufn + K4_AH);
            unsigned* ALn = (unsigned*)(bufn + K4_AL);
            unsigned* BHn = (unsigned*)(bufn + K4_BH);
            #pragma unroll
            for (int i = 0; i < 2; i++) {
                unsigned h0_, l0_, h1_, l1_;
                splitpack(avv[i].x, avv[i].y, h0_, l0_);
                splitpack(avv[i].z, avv[i].w, h1_, l1_);
                *(uint2*)(AHn + (i * 64 + ar) * K2P + aq * 2) = make_uint2(h0_, h1_);
                *(uint2*)(ALn + (i * 64 + ar) * K2P + aq * 2) = make_uint2(l0_, l1_);
            }
            #pragma unroll
            for (int i = 0; i < 4; i++) {
                unsigned h0_, l0_, h1_, l1_;
                splitpack(bvv[i].x, bvv[i].y, h0_, l0_);
                splitpack(bvv[i].z, bvv[i].w, h1_, l1_);
                *(uint2*)(BHn + (i * 64 + br) * K2P + bq * 2) = make_uint2(h0_, h1_);
            }
        }
        __syncthreads();
    }

    #pragma unroll
    for (int mi = 0; mi < 2; mi++) {
        #pragma unroll
        for (int hf = 0; hf < 2; hf++) {
            const int r = wm * 32 + mi * 16 + hf * 8 + g;
            #pragma unroll
            for (int ni = 0; ni < 8; ni++) {
                const int j = j0 + wn * 64 + ni * 8 + t * 2;
                if (j < V) {
                    float2 o2;
                    o2.x = c[mi][ni][hf * 2 + 0] + b2[j];
                    o2.y = c[mi][ni][hf * 2 + 1] + b2[j + 1];
                    *(float2*)(g_logits + (size_t)r * V + j) = o2;
                }
            }
        }
    }
}

// ---------------------------------------------------------------------------
__global__ void k5a1_part()
{
    const int blk = blockIdx.x;
    const int b = blk / 25, ch = blk - b * 25;
    const int t = threadIdx.x;
    const float* lr = g_logits + (size_t)b * V + ch * 2000;
    __shared__ float red[256];

    float mx = -1e30f;
    for (int j = t; j < 2000; j += 256) mx = fmaxf(mx, lr[j]);
    red[t] = mx;
    __syncthreads();
    for (int off = 128; off > 0; off >>= 1) {
        if (t < off) red[t] = fmaxf(red[t], red[t + off]);
        __syncthreads();
    }
    mx = red[0];
    __syncthreads();

    float s = 0.f;
    for (int j = t; j < 2000; j += 256) s += expf(lr[j] - mx);
    red[t] = s;
    __syncthreads();
    for (int off = 128; off > 0; off >>= 1) {
        if (t < off) red[t] += red[t + off];
        __syncthreads();
    }
    if (t == 0) { g_pmax[blk] = mx; g_psum[blk] = red[0]; }
}

__global__ void k5a2_comb()
{
    const int b = blockIdx.x, lane = threadIdx.x;
    float pm = (lane < 25) ? g_pmax[b * 25 + lane] : -1e30f;
    float mx = pm;
    #pragma unroll
    for (int o = 16; o > 0; o >>= 1) mx = fmaxf(mx, __shfl_xor_sync(0xffffffffu, mx, o));
    float v = (lane < 25) ? g_psum[b * 25 + lane] * expf(pm - mx) : 0.f;
    v = wred(v);
    if (lane == 0) { g_rowmax[b] = mx; g_rowinv[b] = 1.f / v; }
}

__global__ void k5b_final(float* __restrict__ out)
{
    const int i = blockIdx.x * 256 + threadIdx.x;
    if (i >= B * VO) return;
    const int b = i / VO;
    const int c = i - b * VO;
    float v = 0.f;
    if (c < V) {
        const float gp = out[OFF_GP + b];
        v = expf(g_logits[(size_t)b * V + c] - g_rowmax[b]) * g_rowinv[b] * gp;
    }
    out[i] = v;
}

__global__ void k5c_scatter(const int* __restrict__ ewo, float* __restrict__ out)
{
    const int i = blockIdx.x * 256 + threadIdx.x;
    if (i >= B * S) return;
    const int b = i / S;
    const float gp = out[OFF_GP + b];
    const float a = out[OFF_AT + i];
    atomicAdd(out + (size_t)b * VO + ewo[i], a * (1.f - gp));
}

// ---------------------------------------------------------------------------
extern "C" void kernel_launch(void* const* d_in, const int* in_sizes, int n_in,
                              void* d_out, int out_size)
{
    const int*   idx      = (const int*)  d_in[0];
    const float* h0       = (const float*)d_in[1];
    const float* c0       = (const float*)d_in[2];
    const float* EO       = (const float*)d_in[3];
    const int*   emask    = (const int*)  d_in[4];
    const float* ctxv     = (const float*)d_in[5];
    const int*   ewo      = (const int*)  d_in[7];
    const float* coverage = (const float*)d_in[8];
    const float* emb      = (const float*)d_in[9];
    const float* Wi       = (const float*)d_in[10];
    const float* bi       = (const float*)d_in[11];
    const float* W_ih     = (const float*)d_in[12];
    const float* W_hh     = (const float*)d_in[13];
    const float* b_ih     = (const float*)d_in[14];
    const float* b_hh     = (const float*)d_in[15];
    const float* att_wh   = (const float*)d_in[16];
    const float* att_ws   = (const float*)d_in[17];
    const float* att_wc   = (const float*)d_in[18];
    const float* att_bc   = (const float*)d_in[19];
    const float* att_v    = (const float*)d_in[20];
    const float* gp_wh    = (const float*)d_in[21];
    const float* gp_bh    = (const float*)d_in[22];
    const float* gp_ws    = (const float*)d_in[23];
    const float* gp_bs    = (const float*)d_in[24];
    const float* gp_wx    = (const float*)d_in[25];
    const float* gp_bx    = (const float*)d_in[26];
    const float* out_w1   = (const float*)d_in[27];
    const float* out_b1   = (const float*)d_in[28];
    const float* out_w2   = (const float*)d_in[29];
    const float* out_b2   = (const float*)d_in[30];
    float* out = (float*)d_out;

    static int attr_done = 0;
    if (!attr_done) {
        cudaFuncSetAttribute(k2_mma, cudaFuncAttributeMaxDynamicSharedMemorySize, K2_SMEM);
        cudaFuncSetAttribute(k4_mma, cudaFuncAttributeMaxDynamicSharedMemorySize, K4_SMEM);
        attr_done = 1;
    }

    k0_wh<<<512, 256>>>(att_wh);
    k1_lstm<<<B, 256>>>(idx, h0, c0, ctxv, emb, Wi, bi, W_ih, W_hh, b_ih, b_hh,
                        att_ws, att_bc, gp_ws, gp_bs, gp_wx, gp_bx, gp_bh, out);
    k2_mma<<<(B * S) / 64, 512, K2_SMEM>>>(EO, att_wc, att_v, coverage, emask);
    k3a_softmax<<<B, 512>>>(coverage, out);
    k3c_ctxpart<<<B * 4, 512>>>(EO, out);
    k3d_ctx<<<B, 512>>>(gp_wh, out);
    {
        dim3 g3b(4, 2);
        k3b_hidden<<<g3b, 256>>>(out_w1, out_b1, out);
    }
    k4_mma<<<(V + 255) / 256, 512, K4_SMEM>>>(out_w2, out_b2);
    k5a1_part<<<B * 25, 256>>>();
    k5a2_comb<<<B, 32>>>();
    k5b_final<<<(B * VO + 255) / 256, 256>>>(out);
    k5c_scatter<<<(B * S + 255) / 256, 256>>>(ewo, out);
}